// round 3
// baseline (speedup 1.0000x reference)
#include <cuda_runtime.h>

#define N_NODES 50000
#define N_EDGES 800000

// -------- static scratch: __device__ globals, referenced only in device code
#define SC_H0  0L                                  // 50000*128 floats
#define SC_H1  (50000L * 128)                      // 50000*256
#define SC_H2  (SC_H1 + 50000L * 256)              // 50000*256
#define SC_AGG (SC_H2 + 50000L * 256)              // 50000*256
__device__ float g_scratch[SC_AGG + 50000L * 256]; // ~179 MB

__device__ int g_deg[N_NODES];
__device__ int g_rowptr[N_NODES + 1];
__device__ int g_cursor[N_NODES];
__device__ int g_srcs[N_EDGES];

// ------------------------------- CSR build --------------------------------
// edge_index is int32: ei[0:E] = src, ei[E:2E] = dst
__global__ void k_zero_deg() {
    int i = blockIdx.x * blockDim.x + threadIdx.x;
    if (i < N_NODES) g_deg[i] = 0;
}

__global__ void k_count(const int* __restrict__ ei) {
    int e = blockIdx.x * blockDim.x + threadIdx.x;
    if (e < N_EDGES) {
        int d = ei[N_EDGES + e];
        if (d >= 0 && d < N_NODES) atomicAdd(&g_deg[d], 1);
    }
}

// single-block serial-chunk scan: 50000 elems, 49 chunks of 1024
__global__ void k_scan() {
    __shared__ int buf[1024];
    __shared__ int s_carry;
    int tid = threadIdx.x;
    if (tid == 0) { s_carry = 0; g_rowptr[0] = 0; }
    __syncthreads();
    for (int base = 0; base < N_NODES; base += 1024) {
        int i = base + tid;
        int v = (i < N_NODES) ? g_deg[i] : 0;
        buf[tid] = v;
        __syncthreads();
        for (int off = 1; off < 1024; off <<= 1) {
            int t = (tid >= off) ? buf[tid - off] : 0;
            __syncthreads();
            buf[tid] += t;
            __syncthreads();
        }
        if (i < N_NODES) g_rowptr[i + 1] = s_carry + buf[tid];
        __syncthreads();
        if (tid == 0) s_carry += buf[1023];
        __syncthreads();
    }
}

__global__ void k_cursor() {
    int i = blockIdx.x * blockDim.x + threadIdx.x;
    if (i < N_NODES) g_cursor[i] = g_rowptr[i];
}

__global__ void k_scatter(const int* __restrict__ ei) {
    int e = blockIdx.x * blockDim.x + threadIdx.x;
    if (e < N_EDGES) {
        int d = ei[N_EDGES + e];
        int s = ei[e];
        if (d >= 0 && d < N_NODES) {
            int p = atomicAdd(&g_cursor[d], 1);
            g_srcs[p] = (s >= 0 && s < N_NODES) ? s : 0;
        }
    }
}

// --------------------------- mean aggregation -----------------------------
// one warp per node; float4 lanes; tables fit in L2 (126 MB)
template <int D>
__global__ void k_agg(long in_off) {
    const float* __restrict__ h = g_scratch + in_off;
    float* __restrict__ out     = g_scratch + SC_AGG;
    int w    = (blockIdx.x * blockDim.x + threadIdx.x) >> 5;
    int lane = threadIdx.x & 31;
    if (w >= N_NODES) return;
    int s0 = g_rowptr[w];
    int s1 = g_rowptr[w + 1];
    float4 a0 = make_float4(0.f, 0.f, 0.f, 0.f);
    float4 a1 = make_float4(0.f, 0.f, 0.f, 0.f);
    for (int e = s0; e < s1; ++e) {
        const float4* r = (const float4*)(h + (size_t)g_srcs[e] * D);
        float4 v = r[lane];
        a0.x += v.x; a0.y += v.y; a0.z += v.z; a0.w += v.w;
        if (D == 256) {
            float4 u = r[lane + 32];
            a1.x += u.x; a1.y += u.y; a1.z += u.z; a1.w += u.w;
        }
    }
    float inv = 1.0f / (float)max(s1 - s0, 1);
    a0.x *= inv; a0.y *= inv; a0.z *= inv; a0.w *= inv;
    float4* o = (float4*)(out + (size_t)w * D);
    o[lane] = a0;
    if (D == 256) {
        a1.x *= inv; a1.y *= inv; a1.z *= inv; a1.w *= inv;
        o[lane + 32] = a1;
    }
}

// ------------------------------ dual GEMM ---------------------------------
// C = A1@W1 (+ A2@W2) + bias (+relu). BM=BN=128, BK=8, 256 thr, 8x8 micro.
// A/C resolved device-side: offset >= 0 -> g_scratch+off, else external ptr.
__global__ void __launch_bounds__(256)
k_gemm(const float* __restrict__ extA, long a1_off, int dual, long a2_off,
       const float* __restrict__ W1, const float* __restrict__ W2,
       const float* __restrict__ bias,
       float* __restrict__ extC, long c_off,
       int M, int K, int Nout, int relu) {
    const float* A1 = (a1_off >= 0) ? g_scratch + a1_off : extA;
    const float* A2 = g_scratch + a2_off;              // only used if dual
    float*       C  = (c_off  >= 0) ? g_scratch + c_off : extC;

    __shared__ float As[8][128];
    __shared__ float Bs[8][128];
    int t  = threadIdx.x;
    int tx = t & 15, ty = t >> 4;
    int row0 = blockIdx.y * 128;
    int n0   = blockIdx.x * 128;

    float acc[8][8];
#pragma unroll
    for (int i = 0; i < 8; ++i)
#pragma unroll
        for (int j = 0; j < 8; ++j) acc[i][j] = 0.f;

    int arow = t >> 1, acol = (t & 1) * 4;
    int brow = t >> 5, bcol = (t & 31) * 4;

    int nphase = dual ? 2 : 1;
    for (int phase = 0; phase < nphase; ++phase) {
        const float* A = phase ? A2 : A1;
        const float* W = phase ? W2 : W1;
        for (int k0 = 0; k0 < K; k0 += 8) {
            float4 av = make_float4(0.f, 0.f, 0.f, 0.f);
            if (row0 + arow < M)
                av = *(const float4*)(A + (size_t)(row0 + arow) * K + k0 + acol);
            float4 bv = *(const float4*)(W + (size_t)(k0 + brow) * Nout + n0 + bcol);
            As[acol + 0][arow] = av.x;
            As[acol + 1][arow] = av.y;
            As[acol + 2][arow] = av.z;
            As[acol + 3][arow] = av.w;
            *(float4*)&Bs[brow][bcol] = bv;
            __syncthreads();
#pragma unroll
            for (int kk = 0; kk < 8; ++kk) {
                float a[8], b[8];
#pragma unroll
                for (int i = 0; i < 8; ++i) a[i] = As[kk][ty + 16 * i];
#pragma unroll
                for (int j = 0; j < 8; ++j) b[j] = Bs[kk][tx + 16 * j];
#pragma unroll
                for (int i = 0; i < 8; ++i)
#pragma unroll
                    for (int j = 0; j < 8; ++j) acc[i][j] += a[i] * b[j];
            }
            __syncthreads();
        }
    }

#pragma unroll
    for (int i = 0; i < 8; ++i) {
        int row = row0 + ty + 16 * i;
        if (row >= M) continue;
#pragma unroll
        for (int j = 0; j < 8; ++j) {
            int col = n0 + tx + 16 * j;
            float v = acc[i][j] + bias[col];
            if (relu) v = fmaxf(v, 0.f);
            C[(size_t)row * Nout + col] = v;
        }
    }
}

// ------------------------------ normalize ---------------------------------
__global__ void k_norm(float* __restrict__ y) {
    int w    = (blockIdx.x * blockDim.x + threadIdx.x) >> 5;
    int lane = threadIdx.x & 31;
    if (w >= N_NODES) return;
    float4* r = (float4*)(y + (size_t)w * 256);
    float4 v0 = r[lane];
    float4 v1 = r[lane + 32];
    float ss = v0.x * v0.x + v0.y * v0.y + v0.z * v0.z + v0.w * v0.w +
               v1.x * v1.x + v1.y * v1.y + v1.z * v1.z + v1.w * v1.w;
#pragma unroll
    for (int o = 16; o > 0; o >>= 1) ss += __shfl_xor_sync(0xffffffffu, ss, o);
    float inv = 1.0f / fmaxf(sqrtf(ss), 1e-12f);
    v0.x *= inv; v0.y *= inv; v0.z *= inv; v0.w *= inv;
    v1.x *= inv; v1.y *= inv; v1.z *= inv; v1.w *= inv;
    r[lane]      = v0;
    r[lane + 32] = v1;
}

// -------------------------------- launch ----------------------------------
extern "C" void kernel_launch(void* const* d_in, const int* in_sizes, int n_in,
                              void* d_out, int out_size) {
    const float* x     = (const float*)d_in[0];
    const int*   ei    = (const int*)d_in[1];     // int32 (JAX x64 disabled)
    const float* pre_W = (const float*)d_in[2];
    const float* pre_b = (const float*)d_in[3];
    const float* W1l   = (const float*)d_in[4];
    const float* b1    = (const float*)d_in[5];
    const float* W1r   = (const float*)d_in[6];
    const float* W2l   = (const float*)d_in[7];
    const float* b2    = (const float*)d_in[8];
    const float* W2r   = (const float*)d_in[9];
    const float* W3l   = (const float*)d_in[10];
    const float* b3    = (const float*)d_in[11];
    const float* W3r   = (const float*)d_in[12];
    float*       out   = (float*)d_out;

    // CSR build (recomputed every call)
    k_zero_deg<<<(N_NODES + 255) / 256, 256>>>();
    k_count<<<(N_EDGES + 255) / 256, 256>>>(ei);
    k_scan<<<1, 1024>>>();
    k_cursor<<<(N_NODES + 255) / 256, 256>>>();
    k_scatter<<<(N_EDGES + 255) / 256, 256>>>(ei);

    dim3 g1(1, (N_NODES + 127) / 128);
    dim3 g2(2, (N_NODES + 127) / 128);
    const int AGG_BLOCKS = (N_NODES + 7) / 8;   // warp per node, 8 warps/block

    // pre: h0 = x @ pre_W + pre_b
    k_gemm<<<g1, 256>>>(x, -1L, 0, 0L, pre_W, nullptr, pre_b,
                        nullptr, SC_H0, N_NODES, 128, 128, 0);

    // layer 1: h1 = relu(mean(h0) @ W1l + h0 @ W1r + b1)
    k_agg<128><<<AGG_BLOCKS, 256>>>(SC_H0);
    k_gemm<<<g2, 256>>>(nullptr, SC_AGG, 1, SC_H0, W1l, W1r, b1,
                        nullptr, SC_H1, N_NODES, 128, 256, 1);

    // layer 2
    k_agg<256><<<AGG_BLOCKS, 256>>>(SC_H1);
    k_gemm<<<g2, 256>>>(nullptr, SC_AGG, 1, SC_H1, W2l, W2r, b2,
                        nullptr, SC_H2, N_NODES, 256, 256, 1);

    // layer 3 (no relu) -> d_out
    k_agg<256><<<AGG_BLOCKS, 256>>>(SC_H2);
    k_gemm<<<g2, 256>>>(nullptr, SC_AGG, 1, SC_H2, W3l, W3r, b3,
                        out, -1L, N_NODES, 256, 256, 0);

    // L2 normalize rows in place
    k_norm<<<AGG_BLOCKS, 256>>>(out);
}

// round 4
// speedup vs baseline: 2.3212x; 2.3212x over previous
#include <cuda_runtime.h>
#include <cstdint>

#define N_NODES 50000
#define N_EDGES 800000

// -------- static scratch: __device__ globals, referenced only in device code
#define SC_H0  0L                                  // 50000*128 floats
#define SC_H1  (50000L * 128)                      // 50000*256
#define SC_H2  (SC_H1 + 50000L * 256)              // 50000*256
#define SC_AGG (SC_H2 + 50000L * 256)              // 50000*256
__device__ float g_scratch[SC_AGG + 50000L * 256]; // ~179 MB

__device__ int g_deg[N_NODES];
__device__ int g_rowptr[N_NODES + 1];
__device__ int g_cursor[N_NODES];
__device__ int g_srcs[N_EDGES];

// ------------------------------- CSR build --------------------------------
__global__ void k_zero_deg() {
    int i = blockIdx.x * blockDim.x + threadIdx.x;
    if (i < N_NODES) g_deg[i] = 0;
}

__global__ void k_count(const int* __restrict__ ei) {
    int e = blockIdx.x * blockDim.x + threadIdx.x;
    if (e < N_EDGES) {
        int d = ei[N_EDGES + e];
        if (d >= 0 && d < N_NODES) atomicAdd(&g_deg[d], 1);
    }
}

__global__ void k_scan() {
    __shared__ int buf[1024];
    __shared__ int s_carry;
    int tid = threadIdx.x;
    if (tid == 0) { s_carry = 0; g_rowptr[0] = 0; }
    __syncthreads();
    for (int base = 0; base < N_NODES; base += 1024) {
        int i = base + tid;
        int v = (i < N_NODES) ? g_deg[i] : 0;
        buf[tid] = v;
        __syncthreads();
        for (int off = 1; off < 1024; off <<= 1) {
            int t = (tid >= off) ? buf[tid - off] : 0;
            __syncthreads();
            buf[tid] += t;
            __syncthreads();
        }
        if (i < N_NODES) g_rowptr[i + 1] = s_carry + buf[tid];
        __syncthreads();
        if (tid == 0) s_carry += buf[1023];
        __syncthreads();
    }
}

__global__ void k_cursor() {
    int i = blockIdx.x * blockDim.x + threadIdx.x;
    if (i < N_NODES) g_cursor[i] = g_rowptr[i];
}

__global__ void k_scatter(const int* __restrict__ ei) {
    int e = blockIdx.x * blockDim.x + threadIdx.x;
    if (e < N_EDGES) {
        int d = ei[N_EDGES + e];
        int s = ei[e];
        if (d >= 0 && d < N_NODES) {
            int p = atomicAdd(&g_cursor[d], 1);
            g_srcs[p] = (s >= 0 && s < N_NODES) ? s : 0;
        }
    }
}

// --------------------------- mean aggregation -----------------------------
template <int D>
__global__ void k_agg(long in_off) {
    const float* __restrict__ h = g_scratch + in_off;
    float* __restrict__ out     = g_scratch + SC_AGG;
    int w    = (blockIdx.x * blockDim.x + threadIdx.x) >> 5;
    int lane = threadIdx.x & 31;
    if (w >= N_NODES) return;
    int s0 = g_rowptr[w];
    int s1 = g_rowptr[w + 1];
    float4 a0 = make_float4(0.f, 0.f, 0.f, 0.f);
    float4 a1 = make_float4(0.f, 0.f, 0.f, 0.f);
    for (int e = s0; e < s1; ++e) {
        const float4* r = (const float4*)(h + (size_t)g_srcs[e] * D);
        float4 v = r[lane];
        a0.x += v.x; a0.y += v.y; a0.z += v.z; a0.w += v.w;
        if (D == 256) {
            float4 u = r[lane + 32];
            a1.x += u.x; a1.y += u.y; a1.z += u.z; a1.w += u.w;
        }
    }
    float inv = 1.0f / (float)max(s1 - s0, 1);
    a0.x *= inv; a0.y *= inv; a0.z *= inv; a0.w *= inv;
    float4* o = (float4*)(out + (size_t)w * D);
    o[lane] = a0;
    if (D == 256) {
        a1.x *= inv; a1.y *= inv; a1.z *= inv; a1.w *= inv;
        o[lane + 32] = a1;
    }
}

// ------------------------- tf32 tensor-core GEMM --------------------------
__device__ __forceinline__ float to_tf32(float x) {
    asm("cvt.rna.tf32.f32 %0, %1;" : "=f"(x) : "f"(x));
    return x;
}

__device__ __forceinline__ void mma_tf32(float* c, const uint32_t* a, const uint32_t* b) {
    asm volatile(
        "mma.sync.aligned.m16n8k8.row.col.f32.tf32.tf32.f32 "
        "{%0,%1,%2,%3}, {%4,%5,%6,%7}, {%8,%9}, {%0,%1,%2,%3};"
        : "+f"(c[0]), "+f"(c[1]), "+f"(c[2]), "+f"(c[3])
        : "r"(a[0]), "r"(a[1]), "r"(a[2]), "r"(a[3]), "r"(b[0]), "r"(b[1]));
}

// C = A1@W1 (+ A2@W2) + bias (+relu).  BM=BN=128, BK=32, 256 threads,
// 8 warps (2x4), warp tile 64x32 of m16n8k8 mma. Conflict-free frag reads:
//   As[128][36]  -> a-frag banks = 4*gid + tig  (all distinct)
//   Bs[32][136]  -> b-frag banks = 8*tig + gid  (all distinct)
__global__ void __launch_bounds__(256)
k_gemm_tc(const float* __restrict__ extA, long a1_off, int dual, long a2_off,
          const float* __restrict__ W1, const float* __restrict__ W2,
          const float* __restrict__ bias,
          float* __restrict__ extC, long c_off,
          int M, int K, int Nout, int relu) {
    const float* A1 = (a1_off >= 0) ? g_scratch + a1_off : extA;
    const float* A2 = g_scratch + a2_off;
    float*       C  = (c_off  >= 0) ? g_scratch + c_off : extC;

    __shared__ float As[128][36];
    __shared__ float Bs[32][136];

    int t    = threadIdx.x;
    int wid  = t >> 5, lane = t & 31;
    int gid  = lane >> 2, tig = lane & 3;
    int wm   = (wid >> 2) * 64;       // warp M offset in block tile
    int wn   = (wid & 3) * 32;        // warp N offset
    int row0 = blockIdx.y * 128;
    int n0   = blockIdx.x * 128;

    float acc[4][4][4];
#pragma unroll
    for (int i = 0; i < 4; ++i)
#pragma unroll
        for (int j = 0; j < 4; ++j)
#pragma unroll
            for (int r = 0; r < 4; ++r) acc[i][j][r] = 0.f;

    int nph = dual ? 2 : 1;
    for (int ph = 0; ph < nph; ++ph) {
        const float* A = ph ? A2 : A1;
        const float* W = ph ? W2 : W1;
        for (int k0 = 0; k0 < K; k0 += 32) {
            // ---- A tile: 128 rows x 32 k (1024 float4, 4 per thread) ----
#pragma unroll
            for (int p = 0; p < 4; ++p) {
                int idx = t + 256 * p;
                int m = idx >> 3, kc = (idx & 7) * 4;
                float4 v = make_float4(0.f, 0.f, 0.f, 0.f);
                if (row0 + m < M)
                    v = *(const float4*)(A + (size_t)(row0 + m) * K + k0 + kc);
                v.x = to_tf32(v.x); v.y = to_tf32(v.y);
                v.z = to_tf32(v.z); v.w = to_tf32(v.w);
                *(float4*)&As[m][kc] = v;
            }
            // ---- B tile: 32 k x 128 n ----
#pragma unroll
            for (int p = 0; p < 4; ++p) {
                int idx = t + 256 * p;
                int kr = idx >> 5, c4 = (idx & 31) * 4;
                float4 v = *(const float4*)(W + (size_t)(k0 + kr) * Nout + n0 + c4);
                v.x = to_tf32(v.x); v.y = to_tf32(v.y);
                v.z = to_tf32(v.z); v.w = to_tf32(v.w);
                *(float4*)&Bs[kr][c4] = v;
            }
            __syncthreads();
#pragma unroll
            for (int ks = 0; ks < 4; ++ks) {
                int kk = ks * 8;
                uint32_t af[4][4], bf[4][2];
#pragma unroll
                for (int i = 0; i < 4; ++i) {
                    int mb = wm + i * 16;
                    af[i][0] = __float_as_uint(As[mb + gid][kk + tig]);
                    af[i][1] = __float_as_uint(As[mb + gid + 8][kk + tig]);
                    af[i][2] = __float_as_uint(As[mb + gid][kk + tig + 4]);
                    af[i][3] = __float_as_uint(As[mb + gid + 8][kk + tig + 4]);
                }
#pragma unroll
                for (int j = 0; j < 4; ++j) {
                    int nb = wn + j * 8;
                    bf[j][0] = __float_as_uint(Bs[kk + tig][nb + gid]);
                    bf[j][1] = __float_as_uint(Bs[kk + tig + 4][nb + gid]);
                }
#pragma unroll
                for (int i = 0; i < 4; ++i)
#pragma unroll
                    for (int j = 0; j < 4; ++j) mma_tf32(acc[i][j], af[i], bf[j]);
            }
            __syncthreads();
        }
    }

    // ---- epilogue: bias (+relu), float2 stores ----
#pragma unroll
    for (int j = 0; j < 4; ++j) {
        int cb = n0 + wn + j * 8 + 2 * tig;
        float bv0 = bias[cb], bv1 = bias[cb + 1];
#pragma unroll
        for (int i = 0; i < 4; ++i) {
            int rb = row0 + wm + i * 16 + gid;
            if (rb < M) {
                float v0 = acc[i][j][0] + bv0, v1 = acc[i][j][1] + bv1;
                if (relu) { v0 = fmaxf(v0, 0.f); v1 = fmaxf(v1, 0.f); }
                *(float2*)(C + (size_t)rb * Nout + cb) = make_float2(v0, v1);
            }
            if (rb + 8 < M) {
                float v2 = acc[i][j][2] + bv0, v3 = acc[i][j][3] + bv1;
                if (relu) { v2 = fmaxf(v2, 0.f); v3 = fmaxf(v3, 0.f); }
                *(float2*)(C + (size_t)(rb + 8) * Nout + cb) = make_float2(v2, v3);
            }
        }
    }
}

// ------------------------------ normalize ---------------------------------
__global__ void k_norm(float* __restrict__ y) {
    int w    = (blockIdx.x * blockDim.x + threadIdx.x) >> 5;
    int lane = threadIdx.x & 31;
    if (w >= N_NODES) return;
    float4* r = (float4*)(y + (size_t)w * 256);
    float4 v0 = r[lane];
    float4 v1 = r[lane + 32];
    float ss = v0.x * v0.x + v0.y * v0.y + v0.z * v0.z + v0.w * v0.w +
               v1.x * v1.x + v1.y * v1.y + v1.z * v1.z + v1.w * v1.w;
#pragma unroll
    for (int o = 16; o > 0; o >>= 1) ss += __shfl_xor_sync(0xffffffffu, ss, o);
    float inv = 1.0f / fmaxf(sqrtf(ss), 1e-12f);
    v0.x *= inv; v0.y *= inv; v0.z *= inv; v0.w *= inv;
    v1.x *= inv; v1.y *= inv; v1.z *= inv; v1.w *= inv;
    r[lane]      = v0;
    r[lane + 32] = v1;
}

// -------------------------------- launch ----------------------------------
extern "C" void kernel_launch(void* const* d_in, const int* in_sizes, int n_in,
                              void* d_out, int out_size) {
    const float* x     = (const float*)d_in[0];
    const int*   ei    = (const int*)d_in[1];     // int32
    const float* pre_W = (const float*)d_in[2];
    const float* pre_b = (const float*)d_in[3];
    const float* W1l   = (const float*)d_in[4];
    const float* b1    = (const float*)d_in[5];
    const float* W1r   = (const float*)d_in[6];
    const float* W2l   = (const float*)d_in[7];
    const float* b2    = (const float*)d_in[8];
    const float* W2r   = (const float*)d_in[9];
    const float* W3l   = (const float*)d_in[10];
    const float* b3    = (const float*)d_in[11];
    const float* W3r   = (const float*)d_in[12];
    float*       out   = (float*)d_out;

    // CSR build (recomputed every call)
    k_zero_deg<<<(N_NODES + 255) / 256, 256>>>();
    k_count<<<(N_EDGES + 255) / 256, 256>>>(ei);
    k_scan<<<1, 1024>>>();
    k_cursor<<<(N_NODES + 255) / 256, 256>>>();
    k_scatter<<<(N_EDGES + 255) / 256, 256>>>(ei);

    dim3 g1(1, (N_NODES + 127) / 128);
    dim3 g2(2, (N_NODES + 127) / 128);
    const int AGG_BLOCKS = (N_NODES + 7) / 8;   // warp per node

    // pre: h0 = x @ pre_W + pre_b
    k_gemm_tc<<<g1, 256>>>(x, -1L, 0, 0L, pre_W, nullptr, pre_b,
                           nullptr, SC_H0, N_NODES, 128, 128, 0);

    // layer 1: h1 = relu(mean(h0) @ W1l + h0 @ W1r + b1)
    k_agg<128><<<AGG_BLOCKS, 256>>>(SC_H0);
    k_gemm_tc<<<g2, 256>>>(nullptr, SC_AGG, 1, SC_H0, W1l, W1r, b1,
                           nullptr, SC_H1, N_NODES, 128, 256, 1);

    // layer 2
    k_agg<256><<<AGG_BLOCKS, 256>>>(SC_H1);
    k_gemm_tc<<<g2, 256>>>(nullptr, SC_AGG, 1, SC_H1, W2l, W2r, b2,
                           nullptr, SC_H2, N_NODES, 256, 256, 1);

    // layer 3 (no relu) -> d_out
    k_agg<256><<<AGG_BLOCKS, 256>>>(SC_H2);
    k_gemm_tc<<<g2, 256>>>(nullptr, SC_AGG, 1, SC_H2, W3l, W3r, b3,
                           out, -1L, N_NODES, 256, 256, 0);

    // L2 normalize rows in place
    k_norm<<<AGG_BLOCKS, 256>>>(out);
}

// round 5
// speedup vs baseline: 2.8609x; 1.2325x over previous
#include <cuda_runtime.h>
#include <cstdint>

#define N_NODES 50000
#define N_EDGES 800000

// -------- static scratch: __device__ globals, referenced only in device code
#define SC_H0  0L                                  // 50000*128 floats
#define SC_H1  (50000L * 128)                      // 50000*256
#define SC_H2  (SC_H1 + 50000L * 256)              // 50000*256
#define SC_AGG (SC_H2 + 50000L * 256)              // 50000*256
__device__ float g_scratch[SC_AGG + 50000L * 256]; // ~179 MB

__device__ int g_deg[N_NODES];
__device__ int g_rowptr[N_NODES + 1];
__device__ int g_cursor[N_NODES];
__device__ int g_srcs[N_EDGES];
__device__ int g_bsum[256];

// ------------------------------- CSR build --------------------------------
__global__ void k_zero_deg() {
    int i = blockIdx.x * blockDim.x + threadIdx.x;
    if (i < N_NODES) g_deg[i] = 0;
}

__global__ void k_count(const int* __restrict__ ei) {
    int e = blockIdx.x * blockDim.x + threadIdx.x;
    if (e < N_EDGES) {
        int d = ei[N_EDGES + e];
        if (d >= 0 && d < N_NODES) atomicAdd(&g_deg[d], 1);
    }
}

// two-level scan: per-block inclusive scan + block sums
__global__ void k_blockscan() {
    __shared__ int buf[256];
    int tid = threadIdx.x;
    int i = blockIdx.x * 256 + tid;
    int v = (i < N_NODES) ? g_deg[i] : 0;
    buf[tid] = v;
    __syncthreads();
#pragma unroll
    for (int off = 1; off < 256; off <<= 1) {
        int t = (tid >= off) ? buf[tid - off] : 0;
        __syncthreads();
        buf[tid] += t;
        __syncthreads();
    }
    if (i < N_NODES) g_rowptr[i + 1] = buf[tid];   // within-block inclusive
    if (tid == 255) g_bsum[blockIdx.x] = buf[255];
}

__global__ void k_scanblocks(int nblocks) {
    __shared__ int buf[256];
    int tid = threadIdx.x;
    int v = (tid < nblocks) ? g_bsum[tid] : 0;
    buf[tid] = v;
    __syncthreads();
#pragma unroll
    for (int off = 1; off < 256; off <<= 1) {
        int t = (tid >= off) ? buf[tid - off] : 0;
        __syncthreads();
        buf[tid] += t;
        __syncthreads();
    }
    g_bsum[tid] = buf[tid] - v;                    // exclusive block offset
}

__global__ void k_add() {
    int tid = threadIdx.x;
    int i = blockIdx.x * 256 + tid;
    if (i < N_NODES) {
        int r = g_rowptr[i + 1] + g_bsum[blockIdx.x];
        g_rowptr[i + 1] = r;
        g_cursor[i] = r - g_deg[i];                // rowptr[i]
        if (i == 0) g_rowptr[0] = 0;
    }
}

__global__ void k_scatter(const int* __restrict__ ei) {
    int e = blockIdx.x * blockDim.x + threadIdx.x;
    if (e < N_EDGES) {
        int d = ei[N_EDGES + e];
        int s = ei[e];
        if (d >= 0 && d < N_NODES) {
            int p = atomicAdd(&g_cursor[d], 1);
            g_srcs[p] = (s >= 0 && s < N_NODES) ? s : 0;
        }
    }
}

// --------------------------- mean aggregation -----------------------------
// one warp per node; 2x unrolled edge loop for MLP; rows live in L2
template <int D>
__global__ void k_agg(long in_off) {
    const float* __restrict__ h = g_scratch + in_off;
    float* __restrict__ out     = g_scratch + SC_AGG;
    int w    = (blockIdx.x * blockDim.x + threadIdx.x) >> 5;
    int lane = threadIdx.x & 31;
    if (w >= N_NODES) return;
    int s0 = g_rowptr[w];
    int s1 = g_rowptr[w + 1];
    float4 a0 = make_float4(0.f, 0.f, 0.f, 0.f);
    float4 a1 = make_float4(0.f, 0.f, 0.f, 0.f);
    int e = s0;
    for (; e + 1 < s1; e += 2) {
        int i0 = g_srcs[e], i1 = g_srcs[e + 1];
        const float4* r0 = (const float4*)(h + (size_t)i0 * D);
        const float4* r1 = (const float4*)(h + (size_t)i1 * D);
        float4 v0 = r0[lane];
        float4 v1 = r1[lane];
        a0.x += v0.x + v1.x; a0.y += v0.y + v1.y;
        a0.z += v0.z + v1.z; a0.w += v0.w + v1.w;
        if (D == 256) {
            float4 u0 = r0[lane + 32];
            float4 u1 = r1[lane + 32];
            a1.x += u0.x + u1.x; a1.y += u0.y + u1.y;
            a1.z += u0.z + u1.z; a1.w += u0.w + u1.w;
        }
    }
    if (e < s1) {
        const float4* r = (const float4*)(h + (size_t)g_srcs[e] * D);
        float4 v = r[lane];
        a0.x += v.x; a0.y += v.y; a0.z += v.z; a0.w += v.w;
        if (D == 256) {
            float4 u = r[lane + 32];
            a1.x += u.x; a1.y += u.y; a1.z += u.z; a1.w += u.w;
        }
    }
    float inv = 1.0f / (float)max(s1 - s0, 1);
    a0.x *= inv; a0.y *= inv; a0.z *= inv; a0.w *= inv;
    float4* o = (float4*)(out + (size_t)w * D);
    o[lane] = a0;
    if (D == 256) {
        a1.x *= inv; a1.y *= inv; a1.z *= inv; a1.w *= inv;
        o[lane + 32] = a1;
    }
}

// ------------------------- tf32 tensor-core GEMM --------------------------
#define AS_STRIDE 36
#define BS_STRIDE 136
#define AS_TILE   (128 * AS_STRIDE)
#define BS_TILE   (32 * BS_STRIDE)
#define GEMM_SMEM_BYTES ((2 * AS_TILE + 2 * BS_TILE) * 4)   // 71680 B

__device__ __forceinline__ float to_tf32(float x) {
    asm("cvt.rna.tf32.f32 %0, %1;" : "=f"(x) : "f"(x));
    return x;
}

__device__ __forceinline__ void mma_tf32(float* c, const uint32_t* a, const uint32_t* b) {
    asm volatile(
        "mma.sync.aligned.m16n8k8.row.col.f32.tf32.tf32.f32 "
        "{%0,%1,%2,%3}, {%4,%5,%6,%7}, {%8,%9}, {%0,%1,%2,%3};"
        : "+f"(c[0]), "+f"(c[1]), "+f"(c[2]), "+f"(c[3])
        : "r"(a[0]), "r"(a[1]), "r"(a[2]), "r"(a[3]), "r"(b[0]), "r"(b[1]));
}

__device__ __forceinline__ void cpa16(uint32_t dst, const void* src, int bytes) {
    asm volatile("cp.async.cg.shared.global [%0], [%1], 16, %2;"
                 :: "r"(dst), "l"(src), "r"(bytes));
}

// C = A1@W1 (+ A2@W2) + bias (+relu). BM=BN=128, BK=32, 2-stage cp.async.
__global__ void __launch_bounds__(256)
k_gemm_tc(const float* __restrict__ extA, long a1_off, int dual, long a2_off,
          const float* __restrict__ W1, const float* __restrict__ W2,
          const float* __restrict__ bias,
          float* __restrict__ extC, long c_off,
          int M, int K, int Nout, int relu) {
    const float* A1 = (a1_off >= 0) ? g_scratch + a1_off : extA;
    const float* A2 = g_scratch + a2_off;
    float*       C  = (c_off  >= 0) ? g_scratch + c_off : extC;

    extern __shared__ float smem[];
    float* AsBase = smem;                       // [2][128][36]
    float* BsBase = smem + 2 * AS_TILE;         // [2][32][136]
    uint32_t as_u32 = (uint32_t)__cvta_generic_to_shared(AsBase);
    uint32_t bs_u32 = (uint32_t)__cvta_generic_to_shared(BsBase);

    int t    = threadIdx.x;
    int wid  = t >> 5, lane = t & 31;
    int gid  = lane >> 2, tig = lane & 3;
    int wm   = (wid >> 2) * 64;
    int wn   = (wid & 3) * 32;
    int row0 = blockIdx.y * 128;
    int n0   = blockIdx.x * 128;

    int kblocks = K >> 5;
    int KT = (dual ? 2 : 1) * kblocks;

    float acc[4][4][4];
#pragma unroll
    for (int i = 0; i < 4; ++i)
#pragma unroll
        for (int j = 0; j < 4; ++j)
#pragma unroll
            for (int r = 0; r < 4; ++r) acc[i][j][r] = 0.f;

    // precomputed load coordinates
    int am = t >> 3, akc = (t & 7) * 4;          // +32 rows per p
    int bk = t >> 5, bc4 = (t & 31) * 4;         // +8 k per p

    // --- async tile issue for iteration 'it' into stage 'st' ---
    auto issue = [&](int it, int st) {
        int ph = it / kblocks;
        int k0 = (it - ph * kblocks) << 5;
        const float* A = ph ? A2 : A1;
        const float* W = ph ? W2 : W1;
#pragma unroll
        for (int p = 0; p < 4; ++p) {
            int m = am + 32 * p;
            bool v = (row0 + m) < M;
            const float* src = A + (size_t)(v ? row0 + m : 0) * K + k0 + akc;
            uint32_t dst = as_u32 + (uint32_t)(st * AS_TILE + m * AS_STRIDE + akc) * 4u;
            cpa16(dst, src, v ? 16 : 0);
        }
#pragma unroll
        for (int p = 0; p < 4; ++p) {
            int kr = bk + 8 * p;
            const float* src = W + (size_t)(k0 + kr) * Nout + n0 + bc4;
            uint32_t dst = bs_u32 + (uint32_t)(st * BS_TILE + kr * BS_STRIDE + bc4) * 4u;
            cpa16(dst, src, 16);
        }
        asm volatile("cp.async.commit_group;");
    };

    issue(0, 0);
    for (int it = 0; it < KT; ++it) {
        if (it + 1 < KT) {
            issue(it + 1, (it + 1) & 1);
            asm volatile("cp.async.wait_group 1;");
        } else {
            asm volatile("cp.async.wait_group 0;");
        }
        __syncthreads();
        const float* Asp = AsBase + (it & 1) * AS_TILE;
        const float* Bsp = BsBase + (it & 1) * BS_TILE;
#pragma unroll
        for (int ks = 0; ks < 4; ++ks) {
            int kk = ks * 8;
            uint32_t af[4][4], bf[4][2];
#pragma unroll
            for (int i = 0; i < 4; ++i) {
                int mb = wm + i * 16;
                af[i][0] = __float_as_uint(to_tf32(Asp[(mb + gid) * AS_STRIDE + kk + tig]));
                af[i][1] = __float_as_uint(to_tf32(Asp[(mb + gid + 8) * AS_STRIDE + kk + tig]));
                af[i][2] = __float_as_uint(to_tf32(Asp[(mb + gid) * AS_STRIDE + kk + tig + 4]));
                af[i][3] = __float_as_uint(to_tf32(Asp[(mb + gid + 8) * AS_STRIDE + kk + tig + 4]));
            }
#pragma unroll
            for (int j = 0; j < 4; ++j) {
                int nb = wn + j * 8;
                bf[j][0] = __float_as_uint(to_tf32(Bsp[(kk + tig) * BS_STRIDE + nb + gid]));
                bf[j][1] = __float_as_uint(to_tf32(Bsp[(kk + tig + 4) * BS_STRIDE + nb + gid]));
            }
#pragma unroll
            for (int i = 0; i < 4; ++i)
#pragma unroll
                for (int j = 0; j < 4; ++j) mma_tf32(acc[i][j], af[i], bf[j]);
        }
        __syncthreads();
    }

    // ---- epilogue: bias (+relu), float2 stores ----
#pragma unroll
    for (int j = 0; j < 4; ++j) {
        int cb = n0 + wn + j * 8 + 2 * tig;
        float bv0 = bias[cb], bv1 = bias[cb + 1];
#pragma unroll
        for (int i = 0; i < 4; ++i) {
            int rb = row0 + wm + i * 16 + gid;
            if (rb < M) {
                float v0 = acc[i][j][0] + bv0, v1 = acc[i][j][1] + bv1;
                if (relu) { v0 = fmaxf(v0, 0.f); v1 = fmaxf(v1, 0.f); }
                *(float2*)(C + (size_t)rb * Nout + cb) = make_float2(v0, v1);
            }
            if (rb + 8 < M) {
                float v2 = acc[i][j][2] + bv0, v3 = acc[i][j][3] + bv1;
                if (relu) { v2 = fmaxf(v2, 0.f); v3 = fmaxf(v3, 0.f); }
                *(float2*)(C + (size_t)(rb + 8) * Nout + cb) = make_float2(v2, v3);
            }
        }
    }
}

// ------------------------------ normalize ---------------------------------
__global__ void k_norm(float* __restrict__ y) {
    int w    = (blockIdx.x * blockDim.x + threadIdx.x) >> 5;
    int lane = threadIdx.x & 31;
    if (w >= N_NODES) return;
    float4* r = (float4*)(y + (size_t)w * 256);
    float4 v0 = r[lane];
    float4 v1 = r[lane + 32];
    float ss = v0.x * v0.x + v0.y * v0.y + v0.z * v0.z + v0.w * v0.w +
               v1.x * v1.x + v1.y * v1.y + v1.z * v1.z + v1.w * v1.w;
#pragma unroll
    for (int o = 16; o > 0; o >>= 1) ss += __shfl_xor_sync(0xffffffffu, ss, o);
    float inv = 1.0f / fmaxf(sqrtf(ss), 1e-12f);
    v0.x *= inv; v0.y *= inv; v0.z *= inv; v0.w *= inv;
    v1.x *= inv; v1.y *= inv; v1.z *= inv; v1.w *= inv;
    r[lane]      = v0;
    r[lane + 32] = v1;
}

// -------------------------------- launch ----------------------------------
extern "C" void kernel_launch(void* const* d_in, const int* in_sizes, int n_in,
                              void* d_out, int out_size) {
    const float* x     = (const float*)d_in[0];
    const int*   ei    = (const int*)d_in[1];     // int32
    const float* pre_W = (const float*)d_in[2];
    const float* pre_b = (const float*)d_in[3];
    const float* W1l   = (const float*)d_in[4];
    const float* b1    = (const float*)d_in[5];
    const float* W1r   = (const float*)d_in[6];
    const float* W2l   = (const float*)d_in[7];
    const float* b2    = (const float*)d_in[8];
    const float* W2r   = (const float*)d_in[9];
    const float* W3l   = (const float*)d_in[10];
    const float* b3    = (const float*)d_in[11];
    const float* W3r   = (const float*)d_in[12];
    float*       out   = (float*)d_out;

    static bool attr_set = false;
    if (!attr_set) {
        cudaFuncSetAttribute(k_gemm_tc, cudaFuncAttributeMaxDynamicSharedMemorySize,
                             GEMM_SMEM_BYTES);
        attr_set = true;
    }

    const int NB = (N_NODES + 255) / 256;   // 196

    // CSR build (recomputed every call)
    k_zero_deg<<<NB, 256>>>();
    k_count<<<(N_EDGES + 255) / 256, 256>>>(ei);
    k_blockscan<<<NB, 256>>>();
    k_scanblocks<<<1, 256>>>(NB);
    k_add<<<NB, 256>>>();
    k_scatter<<<(N_EDGES + 255) / 256, 256>>>(ei);

    dim3 g1(1, (N_NODES + 127) / 128);
    dim3 g2(2, (N_NODES + 127) / 128);
    const int AGG_BLOCKS = (N_NODES + 7) / 8;   // warp per node

    // pre: h0 = x @ pre_W + pre_b
    k_gemm_tc<<<g1, 256, GEMM_SMEM_BYTES>>>(x, -1L, 0, 0L, pre_W, nullptr, pre_b,
                                            nullptr, SC_H0, N_NODES, 128, 128, 0);

    // layer 1: h1 = relu(mean(h0) @ W1l + h0 @ W1r + b1)
    k_agg<128><<<AGG_BLOCKS, 256>>>(SC_H0);
    k_gemm_tc<<<g2, 256, GEMM_SMEM_BYTES>>>(nullptr, SC_AGG, 1, SC_H0, W1l, W1r, b1,
                                            nullptr, SC_H1, N_NODES, 128, 256, 1);

    // layer 2
    k_agg<256><<<AGG_BLOCKS, 256>>>(SC_H1);
    k_gemm_tc<<<g2, 256, GEMM_SMEM_BYTES>>>(nullptr, SC_AGG, 1, SC_H1, W2l, W2r, b2,
                                            nullptr, SC_H2, N_NODES, 256, 256, 1);

    // layer 3 (no relu) -> d_out
    k_agg<256><<<AGG_BLOCKS, 256>>>(SC_H2);
    k_gemm_tc<<<g2, 256, GEMM_SMEM_BYTES>>>(nullptr, SC_AGG, 1, SC_H2, W3l, W3r, b3,
                                            out, -1L, N_NODES, 256, 256, 0);

    // L2 normalize rows in place
    k_norm<<<AGG_BLOCKS, 256>>>(out);
}

// round 7
// speedup vs baseline: 3.0095x; 1.0519x over previous
#include <cuda_runtime.h>
#include <cstdint>

#define N_NODES 50000
#define N_EDGES 800000

// -------- static scratch: __device__ globals, device-code references only --
#define SC_H0  0L                                   // 50000*128
#define SC_H1  (50000L * 128)                       // 50000*256
#define SC_H2  (SC_H1 + 50000L * 256)
#define SC_AGG (SC_H2 + 50000L * 256)
#define SC_X   (SC_AGG + 50000L * 256)              // tf32-rounded x
#define SC_W   (SC_X + 50000L * 128)                // tf32-rounded weights
// rounded-weight sub-offsets (floats, original [K][N] layout)
#define W_PRE (SC_W + 0L)        // 128*128
#define W_1L  (SC_W + 16384L)    // 128*256
#define W_1R  (SC_W + 49152L)    // 128*256
#define W_2L  (SC_W + 81920L)    // 256*256
#define W_2R  (SC_W + 147456L)
#define W_3L  (SC_W + 212992L)
#define W_3R  (SC_W + 278528L)
__device__ float g_scratch[SC_W + 344064L];

__device__ int g_deg[N_NODES];
__device__ int g_rowptr[N_NODES + 1];
__device__ int g_cursor[N_NODES];
__device__ int g_srcs[N_EDGES];
__device__ int g_bsum[256];

__device__ __forceinline__ float to_tf32(float x) {
    asm("cvt.rna.tf32.f32 %0, %1;" : "=f"(x) : "f"(x));
    return x;
}

// ------------------------------- CSR build --------------------------------
__global__ void k_zero_deg() {
    int i = blockIdx.x * blockDim.x + threadIdx.x;
    if (i < N_NODES) g_deg[i] = 0;
}
__global__ void k_count(const int* __restrict__ ei) {
    int e = blockIdx.x * blockDim.x + threadIdx.x;
    if (e < N_EDGES) {
        int d = ei[N_EDGES + e];
        if (d >= 0 && d < N_NODES) atomicAdd(&g_deg[d], 1);
    }
}
__global__ void k_blockscan() {
    __shared__ int buf[256];
    int tid = threadIdx.x;
    int i = blockIdx.x * 256 + tid;
    int v = (i < N_NODES) ? g_deg[i] : 0;
    buf[tid] = v;
    __syncthreads();
#pragma unroll
    for (int off = 1; off < 256; off <<= 1) {
        int t = (tid >= off) ? buf[tid - off] : 0;
        __syncthreads();
        buf[tid] += t;
        __syncthreads();
    }
    if (i < N_NODES) g_rowptr[i + 1] = buf[tid];
    if (tid == 255) g_bsum[blockIdx.x] = buf[255];
}
__global__ void k_scanblocks(int nblocks) {
    __shared__ int buf[256];
    int tid = threadIdx.x;
    int v = (tid < nblocks) ? g_bsum[tid] : 0;
    buf[tid] = v;
    __syncthreads();
#pragma unroll
    for (int off = 1; off < 256; off <<= 1) {
        int t = (tid >= off) ? buf[tid - off] : 0;
        __syncthreads();
        buf[tid] += t;
        __syncthreads();
    }
    g_bsum[tid] = buf[tid] - v;
}
__global__ void k_add() {
    int tid = threadIdx.x;
    int i = blockIdx.x * 256 + tid;
    if (i < N_NODES) {
        int r = g_rowptr[i + 1] + g_bsum[blockIdx.x];
        g_rowptr[i + 1] = r;
        g_cursor[i] = r - g_deg[i];
        if (i == 0) g_rowptr[0] = 0;
    }
}
__global__ void k_scatter(const int* __restrict__ ei) {
    int e = blockIdx.x * blockDim.x + threadIdx.x;
    if (e < N_EDGES) {
        int d = ei[N_EDGES + e];
        int s = ei[e];
        if (d >= 0 && d < N_NODES) {
            int p = atomicAdd(&g_cursor[d], 1);
            g_srcs[p] = (s >= 0 && s < N_NODES) ? s : 0;
        }
    }
}

// --------------------- tf32 pre-rounding (x + weights) --------------------
__global__ void k_round_x(const float* __restrict__ x) {
    int i = blockIdx.x * blockDim.x + threadIdx.x;     // float4 index
    if (i < N_NODES * 128 / 4) {
        float4 v = ((const float4*)x)[i];
        v.x = to_tf32(v.x); v.y = to_tf32(v.y);
        v.z = to_tf32(v.z); v.w = to_tf32(v.w);
        ((float4*)(g_scratch + SC_X))[i] = v;
    }
}

struct RW { const float* p[7]; };
__global__ void k_round_w(RW a) {
    int i = blockIdx.x * blockDim.x + threadIdx.x;     // float4 index, 86016 total
    if (i >= 86016) return;
    const float* src; long dst; int j;
    if      (i < 4096)  { src = a.p[0]; dst = W_PRE; j = i; }
    else if (i < 12288) { src = a.p[1]; dst = W_1L;  j = i - 4096; }
    else if (i < 20480) { src = a.p[2]; dst = W_1R;  j = i - 12288; }
    else if (i < 36864) { src = a.p[3]; dst = W_2L;  j = i - 20480; }
    else if (i < 53248) { src = a.p[4]; dst = W_2R;  j = i - 36864; }
    else if (i < 69632) { src = a.p[5]; dst = W_3L;  j = i - 53248; }
    else                { src = a.p[6]; dst = W_3R;  j = i - 69632; }
    float4 v = ((const float4*)src)[j];
    v.x = to_tf32(v.x); v.y = to_tf32(v.y);
    v.z = to_tf32(v.z); v.w = to_tf32(v.w);
    ((float4*)(g_scratch + dst))[j] = v;
}

// --------------------------- mean aggregation -----------------------------
// one warp per node; L2-resident gather; tf32-rounded output
template <int D>
__global__ void k_agg(long in_off) {
    const float* __restrict__ h = g_scratch + in_off;
    float* __restrict__ out     = g_scratch + SC_AGG;
    int w    = (blockIdx.x * blockDim.x + threadIdx.x) >> 5;
    int lane = threadIdx.x & 31;
    if (w >= N_NODES) return;
    int s0 = g_rowptr[w];
    int s1 = g_rowptr[w + 1];
    float4 a0 = make_float4(0.f, 0.f, 0.f, 0.f);
    float4 a1 = make_float4(0.f, 0.f, 0.f, 0.f);
    int e = s0;
    for (; e + 1 < s1; e += 2) {
        int i0 = g_srcs[e], i1 = g_srcs[e + 1];
        const float4* r0 = (const float4*)(h + (size_t)i0 * D);
        const float4* r1 = (const float4*)(h + (size_t)i1 * D);
        float4 v0 = r0[lane];
        float4 v1 = r1[lane];
        a0.x += v0.x + v1.x; a0.y += v0.y + v1.y;
        a0.z += v0.z + v1.z; a0.w += v0.w + v1.w;
        if (D == 256) {
            float4 u0 = r0[lane + 32];
            float4 u1 = r1[lane + 32];
            a1.x += u0.x + u1.x; a1.y += u0.y + u1.y;
            a1.z += u0.z + u1.z; a1.w += u0.w + u1.w;
        }
    }
    if (e < s1) {
        const float4* r = (const float4*)(h + (size_t)g_srcs[e] * D);
        float4 v = r[lane];
        a0.x += v.x; a0.y += v.y; a0.z += v.z; a0.w += v.w;
        if (D == 256) {
            float4 u = r[lane + 32];
            a1.x += u.x; a1.y += u.y; a1.z += u.z; a1.w += u.w;
        }
    }
    float inv = 1.0f / (float)max(s1 - s0, 1);
    float4* o = (float4*)(out + (size_t)w * D);
    o[lane] = make_float4(to_tf32(a0.x * inv), to_tf32(a0.y * inv),
                          to_tf32(a0.z * inv), to_tf32(a0.w * inv));
    if (D == 256)
        o[lane + 32] = make_float4(to_tf32(a1.x * inv), to_tf32(a1.y * inv),
                                   to_tf32(a1.z * inv), to_tf32(a1.w * inv));
}

// ------------------------- tf32 tensor-core GEMM --------------------------
#define AS_STRIDE 36
#define BS_STRIDE 136
#define AS_TILE   (128 * AS_STRIDE)
#define BS_TILE   (32 * BS_STRIDE)
#define GEMM_SMEM_BYTES ((2 * AS_TILE + 2 * BS_TILE) * 4)   // 71680 B

__device__ __forceinline__ void mma_tf32(float* c, const uint32_t* a, const uint32_t* b) {
    asm volatile(
        "mma.sync.aligned.m16n8k8.row.col.f32.tf32.tf32.f32 "
        "{%0,%1,%2,%3}, {%4,%5,%6,%7}, {%8,%9}, {%0,%1,%2,%3};"
        : "+f"(c[0]), "+f"(c[1]), "+f"(c[2]), "+f"(c[3])
        : "r"(a[0]), "r"(a[1]), "r"(a[2]), "r"(a[3]), "r"(b[0]), "r"(b[1]));
}
__device__ __forceinline__ void cpa16(uint32_t dst, const void* src, int bytes) {
    asm volatile("cp.async.cg.shared.global [%0], [%1], 16, %2;"
                 :: "r"(dst), "l"(src), "r"(bytes));
}

// C = A1@W1 (+ A2@W2) + bias (+relu) (+tf32-round). All operands pre-rounded.
// BM=BN=128, BK=32, 2-stage cp.async, 8 warps, 64x32 warp tile of m16n8k8.
__global__ void __launch_bounds__(256)
k_gemm_tc(long a1_off, int dual, long a2_off,
          long w1_off, long w2_off,
          const float* __restrict__ bias,
          float* __restrict__ extC, long c_off,
          int M, int K, int Nout, int relu, int round_store) {
    const float* A1 = g_scratch + a1_off;
    const float* A2 = g_scratch + a2_off;
    const float* W1 = g_scratch + w1_off;
    const float* W2 = g_scratch + w2_off;
    float*       C  = (c_off >= 0) ? g_scratch + c_off : extC;

    extern __shared__ float smem[];
    float* AsBase = smem;                       // [2][128][36]
    float* BsBase = smem + 2 * AS_TILE;         // [2][32][136]
    uint32_t as_u32 = (uint32_t)__cvta_generic_to_shared(AsBase);
    uint32_t bs_u32 = (uint32_t)__cvta_generic_to_shared(BsBase);

    int t    = threadIdx.x;
    int wid  = t >> 5, lane = t & 31;
    int gid  = lane >> 2, tig = lane & 3;
    int wm   = (wid >> 2) * 64;
    int wn   = (wid & 3) * 32;
    int row0 = blockIdx.y * 128;
    int n0   = blockIdx.x * 128;

    int kblocks = K >> 5;
    int KT = (dual ? 2 : 1) * kblocks;

    float acc[4][4][4];
#pragma unroll
    for (int i = 0; i < 4; ++i)
#pragma unroll
        for (int j = 0; j < 4; ++j)
#pragma unroll
            for (int r = 0; r < 4; ++r) acc[i][j][r] = 0.f;

    int am = t >> 3, akc = (t & 7) * 4;
    int bk = t >> 5, bc4 = (t & 31) * 4;

    auto issue = [&](int it, int st) {
        int ph = it / kblocks;
        int k0 = (it - ph * kblocks) << 5;
        const float* A = ph ? A2 : A1;
        const float* W = ph ? W2 : W1;
#pragma unroll
        for (int p = 0; p < 4; ++p) {
            int m = am + 32 * p;
            bool v = (row0 + m) < M;
            const float* src = A + (size_t)(v ? row0 + m : 0) * K + k0 + akc;
            uint32_t dst = as_u32 + (uint32_t)(st * AS_TILE + m * AS_STRIDE + akc) * 4u;
            cpa16(dst, src, v ? 16 : 0);
        }
#pragma unroll
        for (int p = 0; p < 4; ++p) {
            int kr = bk + 8 * p;
            const float* src = W + (size_t)(k0 + kr) * Nout + n0 + bc4;
            uint32_t dst = bs_u32 + (uint32_t)(st * BS_TILE + kr * BS_STRIDE + bc4) * 4u;
            cpa16(dst, src, 16);
        }
        asm volatile("cp.async.commit_group;");
    };

    issue(0, 0);
    for (int it = 0; it < KT; ++it) {
        if (it + 1 < KT) {
            issue(it + 1, (it + 1) & 1);
            asm volatile("cp.async.wait_group 1;");
        } else {
            asm volatile("cp.async.wait_group 0;");
        }
        __syncthreads();
        const float* Asp = AsBase + (it & 1) * AS_TILE;
        const float* Bsp = BsBase + (it & 1) * BS_TILE;
#pragma unroll
        for (int ks = 0; ks < 4; ++ks) {
            int kk = ks * 8;
            uint32_t af[4][4], bf[4][2];
#pragma unroll
            for (int i = 0; i < 4; ++i) {
                int mb = wm + i * 16;
                af[i][0] = __float_as_uint(Asp[(mb + gid) * AS_STRIDE + kk + tig]);
                af[i][1] = __float_as_uint(Asp[(mb + gid + 8) * AS_STRIDE + kk + tig]);
                af[i][2] = __float_as_uint(Asp[(mb + gid) * AS_STRIDE + kk + tig + 4]);
                af[i][3] = __float_as_uint(Asp[(mb + gid + 8) * AS_STRIDE + kk + tig + 4]);
            }
#pragma unroll
            for (int j = 0; j < 4; ++j) {
                int nb = wn + j * 8;
                bf[j][0] = __float_as_uint(Bsp[(kk + tig) * BS_STRIDE + nb + gid]);
                bf[j][1] = __float_as_uint(Bsp[(kk + tig + 4) * BS_STRIDE + nb + gid]);
            }
#pragma unroll
            for (int i = 0; i < 4; ++i)
#pragma unroll
                for (int j = 0; j < 4; ++j) mma_tf32(acc[i][j], af[i], bf[j]);
        }
        __syncthreads();
    }

    // ---- epilogue: bias (+relu) (+round), float2 stores ----
#pragma unroll
    for (int j = 0; j < 4; ++j) {
        int cb = n0 + wn + j * 8 + 2 * tig;
        float bv0 = bias[cb], bv1 = bias[cb + 1];
#pragma unroll
        for (int i = 0; i < 4; ++i) {
            int rb = row0 + wm + i * 16 + gid;
            if (rb < M) {
                float v0 = acc[i][j][0] + bv0, v1 = acc[i][j][1] + bv1;
                if (relu) { v0 = fmaxf(v0, 0.f); v1 = fmaxf(v1, 0.f); }
                if (round_store) { v0 = to_tf32(v0); v1 = to_tf32(v1); }
                *(float2*)(C + (size_t)rb * Nout + cb) = make_float2(v0, v1);
            }
            if (rb + 8 < M) {
                float v2 = acc[i][j][2] + bv0, v3 = acc[i][j][3] + bv1;
                if (relu) { v2 = fmaxf(v2, 0.f); v3 = fmaxf(v3, 0.f); }
                if (round_store) { v2 = to_tf32(v2); v3 = to_tf32(v3); }
                *(float2*)(C + (size_t)(rb + 8) * Nout + cb) = make_float2(v2, v3);
            }
        }
    }
}

// ------------------------------ normalize ---------------------------------
__global__ void k_norm(float* __restrict__ y) {
    int w    = (blockIdx.x * blockDim.x + threadIdx.x) >> 5;
    int lane = threadIdx.x & 31;
    if (w >= N_NODES) return;
    float4* r = (float4*)(y + (size_t)w * 256);
    float4 v0 = r[lane];
    float4 v1 = r[lane + 32];
    float ss = v0.x * v0.x + v0.y * v0.y + v0.z * v0.z + v0.w * v0.w +
               v1.x * v1.x + v1.y * v1.y + v1.z * v1.z + v1.w * v1.w;
#pragma unroll
    for (int o = 16; o > 0; o >>= 1) ss += __shfl_xor_sync(0xffffffffu, ss, o);
    float inv = 1.0f / fmaxf(sqrtf(ss), 1e-12f);
    v0.x *= inv; v0.y *= inv; v0.z *= inv; v0.w *= inv;
    v1.x *= inv; v1.y *= inv; v1.z *= inv; v1.w *= inv;
    r[lane]      = v0;
    r[lane + 32] = v1;
}

// -------------------------------- launch ----------------------------------
extern "C" void kernel_launch(void* const* d_in, const int* in_sizes, int n_in,
                              void* d_out, int out_size) {
    const float* x     = (const float*)d_in[0];
    const int*   ei    = (const int*)d_in[1];
    const float* pre_W = (const float*)d_in[2];
    const float* pre_b = (const float*)d_in[3];
    const float* W1l   = (const float*)d_in[4];
    const float* b1    = (const float*)d_in[5];
    const float* W1r   = (const float*)d_in[6];
    const float* W2l   = (const float*)d_in[7];
    const float* b2    = (const float*)d_in[8];
    const float* W2r   = (const float*)d_in[9];
    const float* W3l   = (const float*)d_in[10];
    const float* b3    = (const float*)d_in[11];
    const float* W3r   = (const float*)d_in[12];
    float*       out   = (float*)d_out;

    static cudaStream_t s_csr = nullptr;
    static cudaEvent_t  s_ev0 = nullptr, s_ev1 = nullptr;
    if (!s_csr) {
        cudaFuncSetAttribute(k_gemm_tc, cudaFuncAttributeMaxDynamicSharedMemorySize,
                             GEMM_SMEM_BYTES);
        cudaStreamCreateWithFlags(&s_csr, cudaStreamNonBlocking);
        cudaEventCreateWithFlags(&s_ev0, cudaEventDisableTiming);
        cudaEventCreateWithFlags(&s_ev1, cudaEventDisableTiming);
    }

    const int NB = (N_NODES + 255) / 256;

    // ---- fork: CSR build on side stream, overlapped with round + pre-GEMM
    cudaEventRecord(s_ev0, 0);
    cudaStreamWaitEvent(s_csr, s_ev0, 0);
    k_zero_deg<<<NB, 256, 0, s_csr>>>();
    k_count<<<(N_EDGES + 255) / 256, 256, 0, s_csr>>>(ei);
    k_blockscan<<<NB, 256, 0, s_csr>>>();
    k_scanblocks<<<1, 256, 0, s_csr>>>(NB);
    k_add<<<NB, 256, 0, s_csr>>>();
    k_scatter<<<(N_EDGES + 255) / 256, 256, 0, s_csr>>>(ei);
    cudaEventRecord(s_ev1, s_csr);

    // ---- main stream: tf32 pre-rounding + pre-GEMM
    k_round_x<<<(N_NODES * 32 + 255) / 256, 256>>>(x);
    RW rw; rw.p[0] = pre_W; rw.p[1] = W1l; rw.p[2] = W1r;
    rw.p[3] = W2l; rw.p[4] = W2r; rw.p[5] = W3l; rw.p[6] = W3r;
    k_round_w<<<(86016 + 255) / 256, 256>>>(rw);

    dim3 g1(1, (N_NODES + 127) / 128);
    dim3 g2(2, (N_NODES + 127) / 128);
    const int AGG_BLOCKS = (N_NODES + 7) / 8;

    // pre: h0 = x @ pre_W + pre_b (rounded store)
    k_gemm_tc<<<g1, 256, GEMM_SMEM_BYTES>>>(SC_X, 0, 0L, W_PRE, W_PRE, pre_b,
                                            nullptr, SC_H0, N_NODES, 128, 128, 0, 1);

    // ---- join: CSR ready before first gather
    cudaStreamWaitEvent(0, s_ev1, 0);

    // layer 1: h1 = relu(mean(h0) @ W1l + h0 @ W1r + b1)
    k_agg<128><<<AGG_BLOCKS, 256>>>(SC_H0);
    k_gemm_tc<<<g2, 256, GEMM_SMEM_BYTES>>>(SC_AGG, 1, SC_H0, W_1L, W_1R, b1,
                                            nullptr, SC_H1, N_NODES, 128, 256, 1, 1);

    // layer 2
    k_agg<256><<<AGG_BLOCKS, 256>>>(SC_H1);
    k_gemm_tc<<<g2, 256, GEMM_SMEM_BYTES>>>(SC_AGG, 1, SC_H1, W_2L, W_2R, b2,
                                            nullptr, SC_H2, N_NODES, 256, 256, 1, 1);

    // layer 3 (no relu, no rounding) -> d_out
    k_agg<256><<<AGG_BLOCKS, 256>>>(SC_H2);
    k_gemm_tc<<<g2, 256, GEMM_SMEM_BYTES>>>(SC_AGG, 1, SC_H2, W_3L, W_3R, b3,
                                            out, -1L, N_NODES, 256, 256, 0, 0);

    // L2 normalize rows in place
    k_norm<<<AGG_BLOCKS, 256>>>(out);
}

// round 8
// speedup vs baseline: 3.1215x; 1.0372x over previous
#include <cuda_runtime.h>
#include <cuda_bf16.h>
#include <cstdint>

#define N_NODES 50000
#define N_EDGES 800000

// -------- static scratch: __device__ globals, device-code references only --
#define SC_H0  0L                                   // 50000*128
#define SC_H1  (50000L * 128)                       // 50000*256
#define SC_H2  (SC_H1 + 50000L * 256)
#define SC_AGG (SC_H2 + 50000L * 256)
#define SC_X   (SC_AGG + 50000L * 256)              // tf32-rounded x
#define SC_W   (SC_X + 50000L * 128)                // tf32-rounded weights
#define W_PRE (SC_W + 0L)        // 128*128
#define W_1L  (SC_W + 16384L)    // 128*256
#define W_1R  (SC_W + 49152L)    // 128*256
#define W_2L  (SC_W + 81920L)    // 256*256
#define W_2R  (SC_W + 147456L)
#define W_3L  (SC_W + 212992L)
#define W_3R  (SC_W + 278528L)
__device__ float g_scratch[SC_W + 344064L];
__device__ __nv_bfloat16 g_hb[50000L * 256];        // bf16 copy of h (gather path)

__device__ int g_deg[N_NODES];
__device__ int g_rowptr[N_NODES + 1];
__device__ int g_cursor[N_NODES];
__device__ int g_srcs[N_EDGES];
__device__ int g_bsum[256];

__device__ __forceinline__ float to_tf32(float x) {
    asm("cvt.rna.tf32.f32 %0, %1;" : "=f"(x) : "f"(x));
    return x;
}

// ------------------------------- CSR build --------------------------------
__global__ void k_zero_deg() {
    int i = blockIdx.x * blockDim.x + threadIdx.x;
    if (i < N_NODES) g_deg[i] = 0;
}
__global__ void k_count(const int* __restrict__ ei) {
    int e = blockIdx.x * blockDim.x + threadIdx.x;
    if (e < N_EDGES) {
        int d = ei[N_EDGES + e];
        if (d >= 0 && d < N_NODES) atomicAdd(&g_deg[d], 1);
    }
}
__global__ void k_blockscan() {
    __shared__ int buf[256];
    int tid = threadIdx.x;
    int i = blockIdx.x * 256 + tid;
    int v = (i < N_NODES) ? g_deg[i] : 0;
    buf[tid] = v;
    __syncthreads();
#pragma unroll
    for (int off = 1; off < 256; off <<= 1) {
        int t = (tid >= off) ? buf[tid - off] : 0;
        __syncthreads();
        buf[tid] += t;
        __syncthreads();
    }
    if (i < N_NODES) g_rowptr[i + 1] = buf[tid];
    if (tid == 255) g_bsum[blockIdx.x] = buf[255];
}
__global__ void k_scanblocks(int nblocks) {
    __shared__ int buf[256];
    int tid = threadIdx.x;
    int v = (tid < nblocks) ? g_bsum[tid] : 0;
    buf[tid] = v;
    __syncthreads();
#pragma unroll
    for (int off = 1; off < 256; off <<= 1) {
        int t = (tid >= off) ? buf[tid - off] : 0;
        __syncthreads();
        buf[tid] += t;
        __syncthreads();
    }
    g_bsum[tid] = buf[tid] - v;
}
__global__ void k_add() {
    int tid = threadIdx.x;
    int i = blockIdx.x * 256 + tid;
    if (i < N_NODES) {
        int r = g_rowptr[i + 1] + g_bsum[blockIdx.x];
        g_rowptr[i + 1] = r;
        g_cursor[i] = r - g_deg[i];
        if (i == 0) g_rowptr[0] = 0;
    }
}
__global__ void k_scatter(const int* __restrict__ ei) {
    int e = blockIdx.x * blockDim.x + threadIdx.x;
    if (e < N_EDGES) {
        int d = ei[N_EDGES + e];
        int s = ei[e];
        if (d >= 0 && d < N_NODES) {
            int p = atomicAdd(&g_cursor[d], 1);
            g_srcs[p] = (s >= 0 && s < N_NODES) ? s : 0;
        }
    }
}

// --------------------- tf32 pre-rounding (x + weights) --------------------
__global__ void k_round_x(const float* __restrict__ x) {
    int i = blockIdx.x * blockDim.x + threadIdx.x;
    if (i < N_NODES * 128 / 4) {
        float4 v = ((const float4*)x)[i];
        v.x = to_tf32(v.x); v.y = to_tf32(v.y);
        v.z = to_tf32(v.z); v.w = to_tf32(v.w);
        ((float4*)(g_scratch + SC_X))[i] = v;
    }
}

struct RW { const float* p[7]; };
__global__ void k_round_w(RW a) {
    int i = blockIdx.x * blockDim.x + threadIdx.x;
    if (i >= 86016) return;
    const float* src; long dst; int j;
    if      (i < 4096)  { src = a.p[0]; dst = W_PRE; j = i; }
    else if (i < 12288) { src = a.p[1]; dst = W_1L;  j = i - 4096; }
    else if (i < 20480) { src = a.p[2]; dst = W_1R;  j = i - 12288; }
    else if (i < 36864) { src = a.p[3]; dst = W_2L;  j = i - 20480; }
    else if (i < 53248) { src = a.p[4]; dst = W_2R;  j = i - 36864; }
    else if (i < 69632) { src = a.p[5]; dst = W_3L;  j = i - 53248; }
    else                { src = a.p[6]; dst = W_3R;  j = i - 69632; }
    float4 v = ((const float4*)src)[j];
    v.x = to_tf32(v.x); v.y = to_tf32(v.y);
    v.z = to_tf32(v.z); v.w = to_tf32(v.w);
    ((float4*)(g_scratch + dst))[j] = v;
}

// --------------------------- mean aggregation (bf16 in) -------------------
// one warp per node; bf16 rows (half traffic), fp32 accumulate, tf32 out.
template <int D>
__global__ void k_agg() {
    float* __restrict__ out = g_scratch + SC_AGG;
    int w    = (blockIdx.x * blockDim.x + threadIdx.x) >> 5;
    int lane = threadIdx.x & 31;
    if (w >= N_NODES) return;
    int s0 = g_rowptr[w];
    int s1 = g_rowptr[w + 1];
    constexpr int PL = D / 32;                 // floats per lane (4 or 8)
    float a[PL];
#pragma unroll
    for (int i = 0; i < PL; ++i) a[i] = 0.f;

    auto accum = [&](int src) {
        const __nv_bfloat16* row = g_hb + (size_t)src * D;
        if (D == 256) {
            uint4 u = ((const uint4*)row)[lane];            // 8 bf16
            float2 f0 = __bfloat1622float2(*(__nv_bfloat162*)&u.x);
            float2 f1 = __bfloat1622float2(*(__nv_bfloat162*)&u.y);
            float2 f2 = __bfloat1622float2(*(__nv_bfloat162*)&u.z);
            float2 f3 = __bfloat1622float2(*(__nv_bfloat162*)&u.w);
            a[0] += f0.x; a[1] += f0.y; a[2] += f1.x; a[3] += f1.y;
            a[4] += f2.x; a[5] += f2.y; a[6] += f3.x; a[7] += f3.y;
        } else {
            uint2 u = ((const uint2*)row)[lane];            // 4 bf16
            float2 f0 = __bfloat1622float2(*(__nv_bfloat162*)&u.x);
            float2 f1 = __bfloat1622float2(*(__nv_bfloat162*)&u.y);
            a[0] += f0.x; a[1] += f0.y; a[2] += f1.x; a[3] += f1.y;
        }
    };

    int e = s0;
    for (; e + 1 < s1; e += 2) {
        int i0 = g_srcs[e], i1 = g_srcs[e + 1];
        accum(i0);
        accum(i1);
    }
    if (e < s1) accum(g_srcs[e]);

    float inv = 1.0f / (float)max(s1 - s0, 1);
    float* o = out + (size_t)w * D + lane * PL;
#pragma unroll
    for (int i = 0; i < PL; i += 4) {
        float4 v = make_float4(to_tf32(a[i] * inv), to_tf32(a[i + 1] * inv),
                               to_tf32(a[i + 2] * inv), to_tf32(a[i + 3] * inv));
        *(float4*)(o + i) = v;
    }
}

// ------------------------- tf32 tensor-core GEMM --------------------------
#define AS_STRIDE 36
#define BS_STRIDE 136
#define AS_TILE   (128 * AS_STRIDE)
#define BS_TILE   (32 * BS_STRIDE)
#define GEMM_SMEM_BYTES ((2 * AS_TILE + 2 * BS_TILE) * 4)   // 71680 B

__device__ __forceinline__ void mma_tf32(float* c, const uint32_t* a, const uint32_t* b) {
    asm volatile(
        "mma.sync.aligned.m16n8k8.row.col.f32.tf32.tf32.f32 "
        "{%0,%1,%2,%3}, {%4,%5,%6,%7}, {%8,%9}, {%0,%1,%2,%3};"
        : "+f"(c[0]), "+f"(c[1]), "+f"(c[2]), "+f"(c[3])
        : "r"(a[0]), "r"(a[1]), "r"(a[2]), "r"(a[3]), "r"(b[0]), "r"(b[1]));
}
__device__ __forceinline__ void cpa16(uint32_t dst, const void* src, int bytes) {
    asm volatile("cp.async.cg.shared.global [%0], [%1], 16, %2;"
                 :: "r"(dst), "l"(src), "r"(bytes));
}

// C = A1@W1 (+ A2@W2) + bias (+relu) (+tf32-round +bf16 copy for gather).
__global__ void __launch_bounds__(256)
k_gemm_tc(long a1_off, int dual, long a2_off,
          long w1_off, long w2_off,
          const float* __restrict__ bias,
          float* __restrict__ extC, long c_off,
          int M, int K, int Nout, int relu, int round_store) {
    const float* A1 = g_scratch + a1_off;
    const float* A2 = g_scratch + a2_off;
    const float* W1 = g_scratch + w1_off;
    const float* W2 = g_scratch + w2_off;
    float*       C  = (c_off >= 0) ? g_scratch + c_off : extC;

    extern __shared__ float smem[];
    float* AsBase = smem;
    float* BsBase = smem + 2 * AS_TILE;
    uint32_t as_u32 = (uint32_t)__cvta_generic_to_shared(AsBase);
    uint32_t bs_u32 = (uint32_t)__cvta_generic_to_shared(BsBase);

    int t    = threadIdx.x;
    int wid  = t >> 5, lane = t & 31;
    int gid  = lane >> 2, tig = lane & 3;
    int wm   = (wid >> 2) * 64;
    int wn   = (wid & 3) * 32;
    int row0 = blockIdx.y * 128;
    int n0   = blockIdx.x * 128;

    int kblocks = K >> 5;
    int KT = (dual ? 2 : 1) * kblocks;

    float acc[4][4][4];
#pragma unroll
    for (int i = 0; i < 4; ++i)
#pragma unroll
        for (int j = 0; j < 4; ++j)
#pragma unroll
            for (int r = 0; r < 4; ++r) acc[i][j][r] = 0.f;

    int am = t >> 3, akc = (t & 7) * 4;
    int bk = t >> 5, bc4 = (t & 31) * 4;

    auto issue = [&](int it, int st) {
        int ph = it / kblocks;
        int k0 = (it - ph * kblocks) << 5;
        const float* A = ph ? A2 : A1;
        const float* W = ph ? W2 : W1;
#pragma unroll
        for (int p = 0; p < 4; ++p) {
            int m = am + 32 * p;
            bool v = (row0 + m) < M;
            const float* src = A + (size_t)(v ? row0 + m : 0) * K + k0 + akc;
            uint32_t dst = as_u32 + (uint32_t)(st * AS_TILE + m * AS_STRIDE + akc) * 4u;
            cpa16(dst, src, v ? 16 : 0);
        }
#pragma unroll
        for (int p = 0; p < 4; ++p) {
            int kr = bk + 8 * p;
            const float* src = W + (size_t)(k0 + kr) * Nout + n0 + bc4;
            uint32_t dst = bs_u32 + (uint32_t)(st * BS_TILE + kr * BS_STRIDE + bc4) * 4u;
            cpa16(dst, src, 16);
        }
        asm volatile("cp.async.commit_group;");
    };

    issue(0, 0);
    for (int it = 0; it < KT; ++it) {
        if (it + 1 < KT) {
            issue(it + 1, (it + 1) & 1);
            asm volatile("cp.async.wait_group 1;");
        } else {
            asm volatile("cp.async.wait_group 0;");
        }
        __syncthreads();
        const float* Asp = AsBase + (it & 1) * AS_TILE;
        const float* Bsp = BsBase + (it & 1) * BS_TILE;
#pragma unroll
        for (int ks = 0; ks < 4; ++ks) {
            int kk = ks * 8;
            uint32_t af[4][4], bf[4][2];
#pragma unroll
            for (int i = 0; i < 4; ++i) {
                int mb = wm + i * 16;
                af[i][0] = __float_as_uint(Asp[(mb + gid) * AS_STRIDE + kk + tig]);
                af[i][1] = __float_as_uint(Asp[(mb + gid + 8) * AS_STRIDE + kk + tig]);
                af[i][2] = __float_as_uint(Asp[(mb + gid) * AS_STRIDE + kk + tig + 4]);
                af[i][3] = __float_as_uint(Asp[(mb + gid + 8) * AS_STRIDE + kk + tig + 4]);
            }
#pragma unroll
            for (int j = 0; j < 4; ++j) {
                int nb = wn + j * 8;
                bf[j][0] = __float_as_uint(Bsp[(kk + tig) * BS_STRIDE + nb + gid]);
                bf[j][1] = __float_as_uint(Bsp[(kk + tig + 4) * BS_STRIDE + nb + gid]);
            }
#pragma unroll
            for (int i = 0; i < 4; ++i)
#pragma unroll
                for (int j = 0; j < 4; ++j) mma_tf32(acc[i][j], af[i], bf[j]);
        }
        __syncthreads();
    }

    // ---- epilogue: bias (+relu) (+round + bf16 copy) ----
#pragma unroll
    for (int j = 0; j < 4; ++j) {
        int cb = n0 + wn + j * 8 + 2 * tig;
        float bv0 = bias[cb], bv1 = bias[cb + 1];
#pragma unroll
        for (int i = 0; i < 4; ++i) {
            int rb = row0 + wm + i * 16 + gid;
            if (rb < M) {
                float v0 = acc[i][j][0] + bv0, v1 = acc[i][j][1] + bv1;
                if (relu) { v0 = fmaxf(v0, 0.f); v1 = fmaxf(v1, 0.f); }
                if (round_store) {
                    v0 = to_tf32(v0); v1 = to_tf32(v1);
                    *(__nv_bfloat162*)(g_hb + (size_t)rb * Nout + cb) =
                        __floats2bfloat162_rn(v0, v1);
                }
                *(float2*)(C + (size_t)rb * Nout + cb) = make_float2(v0, v1);
            }
            if (rb + 8 < M) {
                float v2 = acc[i][j][2] + bv0, v3 = acc[i][j][3] + bv1;
                if (relu) { v2 = fmaxf(v2, 0.f); v3 = fmaxf(v3, 0.f); }
                if (round_store) {
                    v2 = to_tf32(v2); v3 = to_tf32(v3);
                    *(__nv_bfloat162*)(g_hb + (size_t)(rb + 8) * Nout + cb) =
                        __floats2bfloat162_rn(v2, v3);
                }
                *(float2*)(C + (size_t)(rb + 8) * Nout + cb) = make_float2(v2, v3);
            }
        }
    }
}

// ------------------------------ normalize ---------------------------------
__global__ void k_norm(float* __restrict__ y) {
    int w    = (blockIdx.x * blockDim.x + threadIdx.x) >> 5;
    int lane = threadIdx.x & 31;
    if (w >= N_NODES) return;
    float4* r = (float4*)(y + (size_t)w * 256);
    float4 v0 = r[lane];
    float4 v1 = r[lane + 32];
    float ss = v0.x * v0.x + v0.y * v0.y + v0.z * v0.z + v0.w * v0.w +
               v1.x * v1.x + v1.y * v1.y + v1.z * v1.z + v1.w * v1.w;
#pragma unroll
    for (int o = 16; o > 0; o >>= 1) ss += __shfl_xor_sync(0xffffffffu, ss, o);
    float inv = 1.0f / fmaxf(sqrtf(ss), 1e-12f);
    v0.x *= inv; v0.y *= inv; v0.z *= inv; v0.w *= inv;
    v1.x *= inv; v1.y *= inv; v1.z *= inv; v1.w *= inv;
    r[lane]      = v0;
    r[lane + 32] = v1;
}

// -------------------------------- launch ----------------------------------
extern "C" void kernel_launch(void* const* d_in, const int* in_sizes, int n_in,
                              void* d_out, int out_size) {
    const float* x     = (const float*)d_in[0];
    const int*   ei    = (const int*)d_in[1];
    const float* pre_W = (const float*)d_in[2];
    const float* pre_b = (const float*)d_in[3];
    const float* W1l   = (const float*)d_in[4];
    const float* b1    = (const float*)d_in[5];
    const float* W1r   = (const float*)d_in[6];
    const float* W2l   = (const float*)d_in[7];
    const float* b2    = (const float*)d_in[8];
    const float* W2r   = (const float*)d_in[9];
    const float* W3l   = (const float*)d_in[10];
    const float* b3    = (const float*)d_in[11];
    const float* W3r   = (const float*)d_in[12];
    float*       out   = (float*)d_out;

    static cudaStream_t s_csr = nullptr;
    static cudaEvent_t  s_ev0 = nullptr, s_ev1 = nullptr;
    if (!s_csr) {
        cudaFuncSetAttribute(k_gemm_tc, cudaFuncAttributeMaxDynamicSharedMemorySize,
                             GEMM_SMEM_BYTES);
        cudaStreamCreateWithFlags(&s_csr, cudaStreamNonBlocking);
        cudaEventCreateWithFlags(&s_ev0, cudaEventDisableTiming);
        cudaEventCreateWithFlags(&s_ev1, cudaEventDisableTiming);
    }

    const int NB = (N_NODES + 255) / 256;

    // ---- fork: CSR build on side stream
    cudaEventRecord(s_ev0, 0);
    cudaStreamWaitEvent(s_csr, s_ev0, 0);
    k_zero_deg<<<NB, 256, 0, s_csr>>>();
    k_count<<<(N_EDGES + 255) / 256, 256, 0, s_csr>>>(ei);
    k_blockscan<<<NB, 256, 0, s_csr>>>();
    k_scanblocks<<<1, 256, 0, s_csr>>>(NB);
    k_add<<<NB, 256, 0, s_csr>>>();
    k_scatter<<<(N_EDGES + 255) / 256, 256, 0, s_csr>>>(ei);
    cudaEventRecord(s_ev1, s_csr);

    // ---- main stream: tf32 pre-rounding + pre-GEMM
    k_round_x<<<(N_NODES * 32 + 255) / 256, 256>>>(x);
    RW rw; rw.p[0] = pre_W; rw.p[1] = W1l; rw.p[2] = W1r;
    rw.p[3] = W2l; rw.p[4] = W2r; rw.p[5] = W3l; rw.p[6] = W3r;
    k_round_w<<<(86016 + 255) / 256, 256>>>(rw);

    dim3 g1(1, (N_NODES + 127) / 128);
    dim3 g2(2, (N_NODES + 127) / 128);
    const int AGG_BLOCKS = (N_NODES + 7) / 8;

    // pre: h0 = x @ pre_W + pre_b (round + bf16 copy)
    k_gemm_tc<<<g1, 256, GEMM_SMEM_BYTES>>>(SC_X, 0, 0L, W_PRE, W_PRE, pre_b,
                                            nullptr, SC_H0, N_NODES, 128, 128, 0, 1);

    // ---- join: CSR ready before first gather
    cudaStreamWaitEvent(0, s_ev1, 0);

    // layer 1
    k_agg<128><<<AGG_BLOCKS, 256>>>();
    k_gemm_tc<<<g2, 256, GEMM_SMEM_BYTES>>>(SC_AGG, 1, SC_H0, W_1L, W_1R, b1,
                                            nullptr, SC_H1, N_NODES, 128, 256, 1, 1);

    // layer 2
    k_agg<256><<<AGG_BLOCKS, 256>>>();
    k_gemm_tc<<<g2, 256, GEMM_SMEM_BYTES>>>(SC_AGG, 1, SC_H1, W_2L, W_2R, b2,
                                            nullptr, SC_H2, N_NODES, 256, 256, 1, 1);

    // layer 3 (no relu, no round/bf16) -> d_out
    k_agg<256><<<AGG_BLOCKS, 256>>>();
    k_gemm_tc<<<g2, 256, GEMM_SMEM_BYTES>>>(SC_AGG, 1, SC_H2, W_3L, W_3R, b3,
                                            out, -1L, N_NODES, 256, 256, 0, 0);

    // L2 normalize rows in place
    k_norm<<<AGG_BLOCKS, 256>>>(out);
}

// round 10
// speedup vs baseline: 4.0608x; 1.3009x over previous
#include <cuda_runtime.h>
#include <cuda_fp16.h>
#include <cstdint>

#define N_NODES 50000
#define N_EDGES 800000

// ---------------- fp16 scratch (halfs), device-code references only -------
#define HB_X    0L                      // 50000*128
#define HB_H0   6400000L                // 50000*128
#define HB_H1   12800000L               // 50000*256
#define HB_H2   25600000L               // 50000*256
#define HB_AGG  38400000L               // 50000*256
#define HW_PRE  51200000L               // [128][128]
#define HW_1L   51216384L               // [256][128] (transposed: [N][K])
#define HW_1R   51249152L
#define HW_2L   51281920L               // [256][256]
#define HW_2R   51347456L
#define HW_3L   51412992L
#define HW_3R   51478528L
__device__ __align__(16) __half g_half[51544064L];   // ~103 MB

__device__ int g_deg[N_NODES];
__device__ int g_rowptr[N_NODES + 1];
__device__ int g_cursor[N_NODES];
__device__ int g_srcs[N_EDGES];
__device__ int g_bsum[256];

// ------------------------------- CSR build --------------------------------
__global__ void k_zero_deg() {
    int i = blockIdx.x * blockDim.x + threadIdx.x;
    if (i < N_NODES) g_deg[i] = 0;
}
__global__ void k_count(const int* __restrict__ ei) {
    int e = blockIdx.x * blockDim.x + threadIdx.x;
    if (e < N_EDGES) {
        int d = ei[N_EDGES + e];
        if (d >= 0 && d < N_NODES) atomicAdd(&g_deg[d], 1);
    }
}
__global__ void k_blockscan() {
    __shared__ int buf[256];
    int tid = threadIdx.x;
    int i = blockIdx.x * 256 + tid;
    int v = (i < N_NODES) ? g_deg[i] : 0;
    buf[tid] = v;
    __syncthreads();
#pragma unroll
    for (int off = 1; off < 256; off <<= 1) {
        int t = (tid >= off) ? buf[tid - off] : 0;
        __syncthreads();
        buf[tid] += t;
        __syncthreads();
    }
    if (i < N_NODES) g_rowptr[i + 1] = buf[tid];
    if (tid == 255) g_bsum[blockIdx.x] = buf[255];
}
__global__ void k_scanblocks(int nblocks) {
    __shared__ int buf[256];
    int tid = threadIdx.x;
    int v = (tid < nblocks) ? g_bsum[tid] : 0;
    buf[tid] = v;
    __syncthreads();
#pragma unroll
    for (int off = 1; off < 256; off <<= 1) {
        int t = (tid >= off) ? buf[tid - off] : 0;
        __syncthreads();
        buf[tid] += t;
        __syncthreads();
    }
    g_bsum[tid] = buf[tid] - v;
}
__global__ void k_add() {
    int tid = threadIdx.x;
    int i = blockIdx.x * 256 + tid;
    if (i < N_NODES) {
        int r = g_rowptr[i + 1] + g_bsum[blockIdx.x];
        g_rowptr[i + 1] = r;
        g_cursor[i] = r - g_deg[i];
        if (i == 0) g_rowptr[0] = 0;
    }
}
__global__ void k_scatter(const int* __restrict__ ei) {
    int e = blockIdx.x * blockDim.x + threadIdx.x;
    if (e < N_EDGES) {
        int d = ei[N_EDGES + e];
        int s = ei[e];
        if (d >= 0 && d < N_NODES) {
            int p = atomicAdd(&g_cursor[d], 1);
            g_srcs[p] = (s >= 0 && s < N_NODES) ? s : 0;
        }
    }
}

// ------------------ fp16 conversion: x + transposed weights ---------------
__global__ void k_half_x(const float* __restrict__ x) {
    int i = blockIdx.x * blockDim.x + threadIdx.x;        // float4 index
    if (i < N_NODES * 128 / 4) {
        float4 v = ((const float4*)x)[i];
        __half2 h0 = __floats2half2_rn(v.x, v.y);
        __half2 h1 = __floats2half2_rn(v.z, v.w);
        uint2 u = make_uint2(*(uint32_t*)&h0, *(uint32_t*)&h1);
        ((uint2*)(g_half + HB_X))[i] = u;
    }
}

struct WTJob { const float* W; long out; int K, N; };
struct WTArgs { WTJob j[7]; };
__global__ void k_wt(WTArgs a) {
    WTJob jb = a.j[blockIdx.z];
    __shared__ float tsm[32][33];
    int tx = threadIdx.x, ty = threadIdx.y;               // 32 x 8
    int n0 = blockIdx.x * 32, k0 = blockIdx.y * 32;
    if (n0 >= jb.N || k0 >= jb.K) return;
#pragma unroll
    for (int i = 0; i < 4; ++i)
        tsm[ty + 8 * i][tx] = jb.W[(size_t)(k0 + ty + 8 * i) * jb.N + n0 + tx];
    __syncthreads();
#pragma unroll
    for (int i = 0; i < 4; ++i)
        g_half[jb.out + (size_t)(n0 + ty + 8 * i) * jb.K + k0 + tx] =
            __float2half_rn(tsm[tx][ty + 8 * i]);
}

// --------------------------- mean aggregation (fp16) ----------------------
template <int D>
__global__ void k_agg(long in_off) {
    const __half* __restrict__ h = g_half + in_off;
    __half* __restrict__ out     = g_half + HB_AGG;
    int w    = (blockIdx.x * blockDim.x + threadIdx.x) >> 5;
    int lane = threadIdx.x & 31;
    if (w >= N_NODES) return;
    int s0 = g_rowptr[w];
    int s1 = g_rowptr[w + 1];
    constexpr int PL = D / 32;                 // halfs per lane (4 or 8)
    float a[PL];
#pragma unroll
    for (int i = 0; i < PL; ++i) a[i] = 0.f;

    auto accum = [&](int src) {
        const __half* row = h + (size_t)src * D;
        if (D == 256) {
            uint4 u = ((const uint4*)row)[lane];
            float2 f0 = __half22float2(*(__half2*)&u.x);
            float2 f1 = __half22float2(*(__half2*)&u.y);
            float2 f2 = __half22float2(*(__half2*)&u.z);
            float2 f3 = __half22float2(*(__half2*)&u.w);
            a[0] += f0.x; a[1] += f0.y; a[2] += f1.x; a[3] += f1.y;
            a[4] += f2.x; a[5] += f2.y; a[6] += f3.x; a[7] += f3.y;
        } else {
            uint2 u = ((const uint2*)row)[lane];
            float2 f0 = __half22float2(*(__half2*)&u.x);
            float2 f1 = __half22float2(*(__half2*)&u.y);
            a[0] += f0.x; a[1] += f0.y; a[2] += f1.x; a[3] += f1.y;
        }
    };

    int e = s0;
    for (; e + 1 < s1; e += 2) {
        int i0 = g_srcs[e], i1 = g_srcs[e + 1];
        accum(i0);
        accum(i1);
    }
    if (e < s1) accum(g_srcs[e]);

    float inv = 1.0f / (float)max(s1 - s0, 1);
    __half* o = out + (size_t)w * D + lane * PL;
    if (D == 256) {
        __half2 h0 = __floats2half2_rn(a[0] * inv, a[1] * inv);
        __half2 h1 = __floats2half2_rn(a[2] * inv, a[3] * inv);
        __half2 h2 = __floats2half2_rn(a[4] * inv, a[5] * inv);
        __half2 h3 = __floats2half2_rn(a[6] * inv, a[7] * inv);
        uint4 u = make_uint4(*(uint32_t*)&h0, *(uint32_t*)&h1,
                             *(uint32_t*)&h2, *(uint32_t*)&h3);
        *(uint4*)o = u;
    } else {
        __half2 h0 = __floats2half2_rn(a[0] * inv, a[1] * inv);
        __half2 h1 = __floats2half2_rn(a[2] * inv, a[3] * inv);
        uint2 u = make_uint2(*(uint32_t*)&h0, *(uint32_t*)&h1);
        *(uint2*)o = u;
    }
}

// ------------------------- fp16 tensor-core GEMM --------------------------
#define AT_HALFS 5120                      // 128*40
#define AT_BYTES 10240
#define GEMM_SMEM_BYTES (4 * AT_BYTES)     // A0,A1,B0,B1 = 40960

__device__ __forceinline__ void mma_f16(float* c, const uint32_t* a, const uint32_t* b) {
    asm volatile(
        "mma.sync.aligned.m16n8k16.row.col.f32.f16.f16.f32 "
        "{%0,%1,%2,%3}, {%4,%5,%6,%7}, {%8,%9}, {%0,%1,%2,%3};"
        : "+f"(c[0]), "+f"(c[1]), "+f"(c[2]), "+f"(c[3])
        : "r"(a[0]), "r"(a[1]), "r"(a[2]), "r"(a[3]), "r"(b[0]), "r"(b[1]));
}
__device__ __forceinline__ void cpa16(uint32_t dst, const void* src, int bytes) {
    asm volatile("cp.async.cg.shared.global [%0], [%1], 16, %2;"
                 :: "r"(dst), "l"(src), "r"(bytes));
}

__global__ void __launch_bounds__(256)
k_gemm_f16(long a1_off, int dual, long a2_off,
           long w1_off, long w2_off,
           const float* __restrict__ bias,
           float* __restrict__ extC, long ho_off,
           int M, int K, int Nout, int relu) {
    const __half* A1 = g_half + a1_off;
    const __half* A2 = g_half + a2_off;
    const __half* W1 = g_half + w1_off;
    const __half* W2 = g_half + w2_off;

    extern __shared__ __half hsm[];
    uint32_t smem_u32 = (uint32_t)__cvta_generic_to_shared(hsm);

    int t    = threadIdx.x;
    int wid  = t >> 5, lane = t & 31;
    int gid  = lane >> 2, tig = lane & 3;
    int wm   = (wid >> 2) * 64;
    int wn   = (wid & 3) * 32;
    int row0 = blockIdx.y * 128;
    int n0   = blockIdx.x * 128;

    int kblocks = K >> 5;
    int KT = (dual ? 2 : 1) * kblocks;

    float acc[4][4][4];
#pragma unroll
    for (int i = 0; i < 4; ++i)
#pragma unroll
        for (int j = 0; j < 4; ++j)
#pragma unroll
            for (int r = 0; r < 4; ++r) acc[i][j][r] = 0.f;

    auto issue = [&](int it, int st) {
        int ph = it / kblocks;
        int k0 = (it - ph * kblocks) << 5;
        const __half* A = ph ? A2 : A1;
        const __half* W = ph ? W2 : W1;
#pragma unroll
        for (int p = 0; p < 2; ++p) {
            int idx = t + 256 * p;
            int m = idx >> 2, ch = idx & 3;
            bool v = (row0 + m) < M;
            const __half* src = A + (size_t)(v ? row0 + m : 0) * K + k0 + ch * 8;
            uint32_t dst = smem_u32 + (uint32_t)(st * AT_BYTES + m * 80 + ch * 16);
            cpa16(dst, src, v ? 16 : 0);
        }
#pragma unroll
        for (int p = 0; p < 2; ++p) {
            int idx = t + 256 * p;
            int n = idx >> 2, ch = idx & 3;
            const __half* src = W + (size_t)(n0 + n) * K + k0 + ch * 8;
            uint32_t dst = smem_u32 + (uint32_t)(2 * AT_BYTES + st * AT_BYTES + n * 80 + ch * 16);
            cpa16(dst, src, 16);
        }
        asm volatile("cp.async.commit_group;");
    };

    issue(0, 0);
    for (int it = 0; it < KT; ++it) {
        if (it + 1 < KT) {
            issue(it + 1, (it + 1) & 1);
            asm volatile("cp.async.wait_group 1;");
        } else {
            asm volatile("cp.async.wait_group 0;");
        }
        __syncthreads();
        const __half* Asp = hsm + (it & 1) * AT_HALFS;
        const __half* Bsp = hsm + 2 * AT_HALFS + (it & 1) * AT_HALFS;
#pragma unroll
        for (int ks = 0; ks < 2; ++ks) {
            int kk = ks * 16;
            uint32_t af[4][4], bf[4][2];
#pragma unroll
            for (int i = 0; i < 4; ++i) {
                int mb = wm + i * 16;
                af[i][0] = *(const uint32_t*)(Asp + (mb + gid) * 40 + kk + 2 * tig);
                af[i][1] = *(const uint32_t*)(Asp + (mb + gid + 8) * 40 + kk + 2 * tig);
                af[i][2] = *(const uint32_t*)(Asp + (mb + gid) * 40 + kk + 8 + 2 * tig);
                af[i][3] = *(const uint32_t*)(Asp + (mb + gid + 8) * 40 + kk + 8 + 2 * tig);
            }
#pragma unroll
            for (int j = 0; j < 4; ++j) {
                int nb = wn + j * 8;
                bf[j][0] = *(const uint32_t*)(Bsp + (nb + gid) * 40 + kk + 2 * tig);
                bf[j][1] = *(const uint32_t*)(Bsp + (nb + gid) * 40 + kk + 8 + 2 * tig);
            }
#pragma unroll
            for (int i = 0; i < 4; ++i)
#pragma unroll
                for (int j = 0; j < 4; ++j) mma_f16(acc[i][j], af[i], bf[j]);
        }
        __syncthreads();
    }

#pragma unroll
    for (int j = 0; j < 4; ++j) {
        int cb = n0 + wn + j * 8 + 2 * tig;
        float bv0 = bias[cb], bv1 = bias[cb + 1];
#pragma unroll
        for (int i = 0; i < 4; ++i) {
            int rb = row0 + wm + i * 16 + gid;
            if (rb < M) {
                float v0 = acc[i][j][0] + bv0, v1 = acc[i][j][1] + bv1;
                if (relu) { v0 = fmaxf(v0, 0.f); v1 = fmaxf(v1, 0.f); }
                if (ho_off >= 0)
                    *(__half2*)(g_half + ho_off + (size_t)rb * Nout + cb) =
                        __floats2half2_rn(v0, v1);
                else
                    *(float2*)(extC + (size_t)rb * Nout + cb) = make_float2(v0, v1);
            }
            if (rb + 8 < M) {
                float v2 = acc[i][j][2] + bv0, v3 = acc[i][j][3] + bv1;
                if (relu) { v2 = fmaxf(v2, 0.f); v3 = fmaxf(v3, 0.f); }
                if (ho_off >= 0)
                    *(__half2*)(g_half + ho_off + (size_t)(rb + 8) * Nout + cb) =
                        __floats2half2_rn(v2, v3);
                else
                    *(float2*)(extC + (size_t)(rb + 8) * Nout + cb) = make_float2(v2, v3);
            }
        }
    }
}

// ------------------------------ normalize ---------------------------------
__global__ void k_norm(float* __restrict__ y) {
    int w    = (blockIdx.x * blockDim.x + threadIdx.x) >> 5;
    int lane = threadIdx.x & 31;
    if (w >= N_NODES) return;
    float4* r = (float4*)(y + (size_t)w * 256);
    float4 v0 = r[lane];
    float4 v1 = r[lane + 32];
    float ss = v0.x * v0.x + v0.y * v0.y + v0.z * v0.z + v0.w * v0.w +
               v1.x * v1.x + v1.y * v1.y + v1.z * v1.z + v1.w * v1.w;
#pragma unroll
    for (int o = 16; o > 0; o >>= 1) ss += __shfl_xor_sync(0xffffffffu, ss, o);
    float inv = 1.0f / fmaxf(sqrtf(ss), 1e-12f);
    v0.x *= inv; v0.y *= inv; v0.z *= inv; v0.w *= inv;
    v1.x *= inv; v1.y *= inv; v1.z *= inv; v1.w *= inv;
    r[lane]      = v0;
    r[lane + 32] = v1;
}

// -------------------------------- launch ----------------------------------
extern "C" void kernel_launch(void* const* d_in, const int* in_sizes, int n_in,
                              void* d_out, int out_size) {
    const float* x     = (const float*)d_in[0];
    const int*   ei    = (const int*)d_in[1];
    const float* pre_W = (const float*)d_in[2];
    const float* pre_b = (const float*)d_in[3];
    const float* W1l   = (const float*)d_in[4];
    const float* b1    = (const float*)d_in[5];
    const float* W1r   = (const float*)d_in[6];
    const float* W2l   = (const float*)d_in[7];
    const float* b2    = (const float*)d_in[8];
    const float* W2r   = (const float*)d_in[9];
    const float* W3l   = (const float*)d_in[10];
    const float* b3    = (const float*)d_in[11];
    const float* W3r   = (const float*)d_in[12];
    float*       out   = (float*)d_out;

    static cudaStream_t s_csr = nullptr;
    static cudaEvent_t  s_ev0 = nullptr, s_ev1 = nullptr;
    if (!s_csr) {
        cudaFuncSetAttribute(k_gemm_f16, cudaFuncAttributeMaxDynamicSharedMemorySize,
                             GEMM_SMEM_BYTES);
        cudaStreamCreateWithFlags(&s_csr, cudaStreamNonBlocking);
        cudaEventCreateWithFlags(&s_ev0, cudaEventDisableTiming);
        cudaEventCreateWithFlags(&s_ev1, cudaEventDisableTiming);
    }

    const int NB = (N_NODES + 255) / 256;

    // ---- fork: CSR build on side stream
    cudaEventRecord(s_ev0, 0);
    cudaStreamWaitEvent(s_csr, s_ev0, 0);
    k_zero_deg<<<NB, 256, 0, s_csr>>>();
    k_count<<<(N_EDGES + 255) / 256, 256, 0, s_csr>>>(ei);
    k_blockscan<<<NB, 256, 0, s_csr>>>();
    k_scanblocks<<<1, 256, 0, s_csr>>>(NB);
    k_add<<<NB, 256, 0, s_csr>>>();
    k_scatter<<<(N_EDGES + 255) / 256, 256, 0, s_csr>>>(ei);
    cudaEventRecord(s_ev1, s_csr);

    // ---- main stream: fp16 conversions + pre-GEMM
    k_half_x<<<(N_NODES * 32 + 255) / 256, 256>>>(x);
    WTArgs wa;
    wa.j[0] = { pre_W, HW_PRE, 128, 128 };
    wa.j[1] = { W1l,   HW_1L,  128, 256 };
    wa.j[2] = { W1r,   HW_1R,  128, 256 };
    wa.j[3] = { W2l,   HW_2L,  256, 256 };
    wa.j[4] = { W2r,   HW_2R,  256, 256 };
    wa.j[5] = { W3l,   HW_3L,  256, 256 };
    wa.j[6] = { W3r,   HW_3R,  256, 256 };
    k_wt<<<dim3(8, 8, 7), dim3(32, 8)>>>(wa);

    dim3 g1(1, (N_NODES + 127) / 128);
    dim3 g2(2, (N_NODES + 127) / 128);
    const int AGG_BLOCKS = (N_NODES + 7) / 8;

    // pre: h0 = x @ pre_W + pre_b  -> fp16 h0
    k_gemm_f16<<<g1, 256, GEMM_SMEM_BYTES>>>(HB_X, 0, 0L, HW_PRE, HW_PRE, pre_b,
                                             nullptr, HB_H0, N_NODES, 128, 128, 0);

    // ---- join: CSR ready before first gather
    cudaStreamWaitEvent(0, s_ev1, 0);

    // layer 1: h1 = relu(mean(h0)@W1l + h0@W1r + b1) -> fp16 h1
    k_agg<128><<<AGG_BLOCKS, 256>>>(HB_H0);
    k_gemm_f16<<<g2, 256, GEMM_SMEM_BYTES>>>(HB_AGG, 1, HB_H0, HW_1L, HW_1R, b1,
                                             nullptr, HB_H1, N_NODES, 128, 256, 1);

    // layer 2 -> fp16 h2
    k_agg<256><<<AGG_BLOCKS, 256>>>(HB_H1);
    k_gemm_f16<<<g2, 256, GEMM_SMEM_BYTES>>>(HB_AGG, 1, HB_H1, HW_2L, HW_2R, b2,
                                             nullptr, HB_H2, N_NODES, 256, 256, 1);

    // layer 3 (no relu) -> fp32 d_out
    k_agg<256><<<AGG_BLOCKS, 256>>>(HB_H2);
    k_gemm_f16<<<g2, 256, GEMM_SMEM_BYTES>>>(HB_AGG, 1, HB_H2, HW_3L, HW_3R, b3,
                                             out, -1L, N_NODES, 256, 256, 0);

    // L2 normalize rows in place
    k_norm<<<AGG_BLOCKS, 256>>>(out);
}